// round 10
// baseline (speedup 1.0000x reference)
#include <cuda_runtime.h>
#include <cuda_fp16.h>
#include <cstdint>

// ---------------------------------------------------------------------------
// NeuralCDE rollout — EVERYTHING in one persistent dependency-tracked kernel.
//   tasks: W21=(W2@W1a)^T | g=h16(x0@Wpe+b_pe) | z0h=h16(x0@Whi+b_hi)
//          q2=h16(g@W1b + c) | y0: w=z0@W1a, u=tanh(w+dt q2+b1t), S=u
//          49x chain: w += dt u@W21 ; u = tanh(w + t q2 + b1t) ; S += u
//          W2ro=(W2@Wro)^T | o1=z0@Wro | out = o1 + dt S@W2ro + b2ro
// Pre-launch: transposes, fp16 conversions, c/b1t/b2ro vectors, counter reset.
// ---------------------------------------------------------------------------

static constexpr int BATCH = 8192;
static constexpr int DIN   = 1024;
static constexpr int PATHD = 256;
static constexpr int HID   = 1024;
static constexpr int NSTEP = 50;
static constexpr int NCHAIN = NSTEP - 1;     // 49
static constexpr int ROWB  = BATCH / 128;    // 64

// slot layout
static constexpr int S_W21  = 0;                    // 64
static constexpr int S_G    = S_W21 + 64;           // 128
static constexpr int S_Z0   = S_G + 128;            // 512
static constexpr int S_Q    = S_Z0 + 512;           // 512
static constexpr int S_Y0   = S_Q + 512;            // 512
static constexpr int S_CH   = S_Y0 + 512;           // 49*512
static constexpr int S_W2RO = S_CH + NCHAIN * 512;  // 64
static constexpr int S_O1   = S_W2RO + 64;          // 512
static constexpr int S_FIN  = S_O1 + 512;           // 512
static constexpr int S_END  = S_FIN + 512;

// counter rows: 0=g 1=z0 2=q 3=y0 4..52=chain 53=o1
static constexpr int NCTR = 54;

// ---------------- device scratch ----------------
__device__ __half x0h_buf[(size_t)BATCH * DIN];
__device__ __half gh_buf [(size_t)BATCH * PATHD];
__device__ __half qh_buf [(size_t)BATCH * HID];
__device__ __half z0h_buf[(size_t)BATCH * HID];
__device__ __half uh_buf [(size_t)BATCH * HID];
__device__ __half Sh_buf [(size_t)BATCH * HID];
__device__ float  y_buf  [(size_t)BATCH * HID];
__device__ float  S_buf  [(size_t)BATCH * HID];
__device__ float  o1_buf [(size_t)BATCH * HID];
__device__ __half WpeT  [(size_t)PATHD * DIN];
__device__ __half WhiT  [(size_t)HID * DIN];
__device__ __half W1aT  [(size_t)HID * HID];
__device__ __half W1bT  [(size_t)HID * PATHD];
__device__ __half WroT  [(size_t)HID * HID];
__device__ __half W2h   [(size_t)HID * HID];
__device__ __half W21T_b[(size_t)HID * HID];
__device__ __half W2roT_b[(size_t)HID * HID];
__device__ float  cvec_b[HID];
__device__ float  b1t_b [HID];
__device__ float  b2ro_b[HID];

__device__ unsigned int g_done[NCTR][ROWB];
__device__ unsigned int g_cw21, g_cw2ro;
__device__ unsigned int g_tile_ctr;

// ---------------- tile configuration ----------------
static constexpr int BM = 128, BN = 128, BK = 32;
static constexpr int STAGES = 4, NTHREADS = 256;
static constexpr int STR  = BK + 8;
static constexpr int ASZ  = BM * STR;
static constexpr int BSZ  = BN * STR;
static constexpr int SMEM_BYTES = STAGES * (ASZ + BSZ) * 2; // 81920

__device__ __forceinline__ void ldmx4(uint32_t& r0, uint32_t& r1,
                                      uint32_t& r2, uint32_t& r3, uint32_t a) {
    asm volatile("ldmatrix.sync.aligned.m8n8.x4.shared.b16 {%0,%1,%2,%3}, [%4];"
                 : "=r"(r0), "=r"(r1), "=r"(r2), "=r"(r3) : "r"(a));
}
__device__ __forceinline__ float tanh_ap(float x) {
    float y;
    asm("tanh.approx.f32 %0, %1;" : "=f"(y) : "f"(x));
    return y;
}
__device__ __forceinline__ void spin_ge(volatile unsigned int* c, unsigned int v) {
    while (*c < v) __nanosleep(64);
}

// acc = A[bm*128.., :K] @ B[bn*128.., :K]^T
__device__ __forceinline__ void mainloop_f16(
    const __half* __restrict__ A, const __half* __restrict__ Bw,
    int K, int bm, int bn, __half* As, __half* Bs,
    float (&acc)[4][4][4])
{
    const int tid  = threadIdx.x;
    const int wid  = tid >> 5, lane = tid & 31;
    const int warp_m = wid & 1, warp_n = wid >> 1;
    const int KT = K / BK;

#pragma unroll
    for (int a = 0; a < 4; ++a)
#pragma unroll
        for (int b = 0; b < 4; ++b)
#pragma unroll
            for (int c = 0; c < 4; ++c) acc[a][b][c] = 0.f;

    auto load_tile = [&](int kt, int stage) {
        const __half* Ag = A + (size_t)(bm * BM) * K + (size_t)kt * BK;
        __half* Asb = As + stage * ASZ;
#pragma unroll
        for (int i = 0; i < 2; ++i) {
            int lin = i * NTHREADS + tid;
            int r = lin >> 2, c = (lin & 3) << 3;
            uint32_t sa = (uint32_t)__cvta_generic_to_shared(Asb + r * STR + c);
            asm volatile("cp.async.cg.shared.global [%0], [%1], 16;"
                         :: "r"(sa), "l"(Ag + (size_t)r * K + c));
        }
        const __half* Bg = Bw + (size_t)(bn * BN) * K + (size_t)kt * BK;
        __half* Bsb = Bs + stage * BSZ;
#pragma unroll
        for (int i = 0; i < 2; ++i) {
            int lin = i * NTHREADS + tid;
            int r = lin >> 2, c = (lin & 3) << 3;
            uint32_t sa = (uint32_t)__cvta_generic_to_shared(Bsb + r * STR + c);
            asm volatile("cp.async.cg.shared.global [%0], [%1], 16;"
                         :: "r"(sa), "l"(Bg + (size_t)r * K + c));
        }
        asm volatile("cp.async.commit_group;");
    };

    const int a_row  = warp_m * 64 + (lane & 15);
    const int a_koff = (lane >> 4) << 3;
    const int b_row  = warp_n * 32 + (lane & 7) + ((lane >> 4) << 3);
    const int b_koff = ((lane >> 3) & 1) << 3;

    for (int s = 0; s < STAGES - 1 && s < KT; ++s) load_tile(s, s);

    for (int kt = 0; kt < KT; ++kt) {
        if (kt < KT - (STAGES - 1))
            asm volatile("cp.async.wait_group %0;" :: "n"(STAGES - 2));
        else
            asm volatile("cp.async.wait_group 0;");
        __syncthreads();

        int pf = kt + STAGES - 1;
        if (pf < KT) load_tile(pf, pf % STAGES);

        const __half* Asb = As + (kt % STAGES) * ASZ;
        const __half* Bsb = Bs + (kt % STAGES) * BSZ;
        const uint32_t a_base = (uint32_t)__cvta_generic_to_shared(
            Asb + (size_t)a_row * STR + a_koff);
        const uint32_t b_base = (uint32_t)__cvta_generic_to_shared(
            Bsb + (size_t)b_row * STR + b_koff);

#pragma unroll
        for (int ks = 0; ks < BK / 16; ++ks) {
            uint32_t af[4][4], bf[4][2];
#pragma unroll
            for (int mi = 0; mi < 4; ++mi)
                ldmx4(af[mi][0], af[mi][1], af[mi][2], af[mi][3],
                      a_base + (mi * 16 * STR + ks * 16) * 2);
#pragma unroll
            for (int np = 0; np < 2; ++np)
                ldmx4(bf[np*2][0], bf[np*2][1], bf[np*2+1][0], bf[np*2+1][1],
                      b_base + (np * 16 * STR + ks * 16) * 2);
#pragma unroll
            for (int mi = 0; mi < 4; ++mi)
#pragma unroll
                for (int ni = 0; ni < 4; ++ni) {
                    asm volatile(
                        "mma.sync.aligned.m16n8k16.row.col.f32.f16.f16.f32 "
                        "{%0,%1,%2,%3}, {%4,%5,%6,%7}, {%8,%9}, {%0,%1,%2,%3};"
                        : "+f"(acc[mi][ni][0]), "+f"(acc[mi][ni][1]),
                          "+f"(acc[mi][ni][2]), "+f"(acc[mi][ni][3])
                        : "r"(af[mi][0]), "r"(af[mi][1]), "r"(af[mi][2]), "r"(af[mi][3]),
                          "r"(bf[ni][0]), "r"(bf[ni][1]));
                }
        }
    }
}

// ---------------------------------------------------------------------------
// THE persistent kernel
// ---------------------------------------------------------------------------
__global__ __launch_bounds__(NTHREADS, 2)
void cde_all(const __half* __restrict__ x0h,
             const __half* __restrict__ wpe, const __half* __restrict__ whi,
             const __half* __restrict__ w1a, const __half* __restrict__ w1b,
             const __half* __restrict__ wro, const __half* __restrict__ w2h,
             __half* __restrict__ w21, __half* __restrict__ w2ro,
             __half* __restrict__ gh, __half* __restrict__ qh,
             __half* __restrict__ z0h, __half* __restrict__ uh,
             __half* __restrict__ Sh,
             float* __restrict__ y, float* __restrict__ S,
             float* __restrict__ o1, float* __restrict__ out,
             const float* __restrict__ b_pe, const float* __restrict__ b_hi,
             const float* __restrict__ cv, const float* __restrict__ b1t,
             const float* __restrict__ b2ro, float dt)
{
    extern __shared__ __half smem[];
    __half* As = smem;
    __half* Bs = smem + STAGES * ASZ;
    __shared__ unsigned int s_tile;

    const int tid = threadIdx.x, wid = tid >> 5, lane = tid & 31;
    const int gid = lane >> 2, tig = lane & 3;

    while (true) {
        if (tid == 0) s_tile = atomicAdd(&g_tile_ctr, 1u);
        __syncthreads();
        const unsigned int v = s_tile;
        if (v >= (unsigned)S_END) break;

        int kind, gidx = 0, t;
        if (v < (unsigned)S_G)         { kind = 0; t = v - S_W21; }
        else if (v < (unsigned)S_Z0)   { kind = 1; t = v - S_G; }
        else if (v < (unsigned)S_Q)    { kind = 2; t = v - S_Z0; }
        else if (v < (unsigned)S_Y0)   { kind = 3; t = v - S_Q; }
        else if (v < (unsigned)S_CH)   { kind = 4; t = v - S_Y0; }
        else if (v < (unsigned)S_W2RO) { kind = 5; gidx = (v - S_CH) >> 9; t = (v - S_CH) & 511; }
        else if (v < (unsigned)S_O1)   { kind = 6; t = v - S_W2RO; }
        else if (v < (unsigned)S_FIN)  { kind = 7; t = v - S_O1; }
        else                           { kind = 8; t = v - S_FIN; }

        int bm, bn;
        if (kind == 1) { bm = t >> 1; bn = t & 1; }
        else           { bm = t >> 3; bn = t & 7; }

        // ---- dependencies (tid 0 spins) ----
        if (tid == 0) {
            if (kind == 3) {                     // q: needs g row bm (2 tiles)
                spin_ge(&g_done[0][bm], 2u);
            } else if (kind == 4) {              // y0: z0 row + q row
                spin_ge(&g_done[1][bm], 8u);
                spin_ge(&g_done[2][bm], 8u);
            } else if (kind == 5) {
                if (gidx == 0) {
                    spin_ge(&g_done[3][bm], 8u);
                    spin_ge(&g_cw21, 64u);
                } else {
                    spin_ge(&g_done[4 + gidx - 1][bm], 8u);
                }
            } else if (kind == 7) {              // o1: z0 row
                spin_ge(&g_done[1][bm], 8u);
            } else if (kind == 8) {              // final
                spin_ge(&g_done[4 + NCHAIN - 1][bm], 8u);
                spin_ge(&g_done[53][bm], 8u);
                spin_ge(&g_cw2ro, 64u);
            }
            __threadfence();
        }
        __syncthreads();

        const __half* A;
        const __half* Bw;
        int K = HID;
        if (kind == 0)      { A = w1a; Bw = w2h; }
        else if (kind == 1) { A = x0h; Bw = wpe; K = DIN; }
        else if (kind == 2) { A = x0h; Bw = whi; K = DIN; }
        else if (kind == 3) { A = gh;  Bw = w1b; K = PATHD; }
        else if (kind == 4) { A = z0h; Bw = w1a; }
        else if (kind == 5) { A = uh;  Bw = w21; }
        else if (kind == 6) { A = wro; Bw = w2h; }
        else if (kind == 7) { A = z0h; Bw = wro; }
        else                { A = Sh;  Bw = w2ro; }

        float acc[4][4][4];
        mainloop_f16(A, Bw, K, bm, bn, As, Bs, acc);

        const int N = (kind == 1) ? PATHD : HID;
        const int rbase = bm * BM + (wid & 1) * 64;
        const int cbase = bn * BN + (wid >> 1) * 32;

#pragma unroll
        for (int mi = 0; mi < 4; ++mi)
#pragma unroll
            for (int h2 = 0; h2 < 2; ++h2) {
                int row = rbase + mi * 16 + h2 * 8 + gid;
#pragma unroll
                for (int ni = 0; ni < 4; ++ni) {
                    int col = cbase + ni * 8 + tig * 2;
                    size_t off = (size_t)row * N + col;
                    float a0 = acc[mi][ni][h2 * 2 + 0];
                    float a1 = acc[mi][ni][h2 * 2 + 1];

                    if (kind == 0) {
                        *reinterpret_cast<__half2*>(w21 + off) =
                            __floats2half2_rn(a0, a1);
                    } else if (kind == 1) {
                        *reinterpret_cast<__half2*>(gh + off) = __floats2half2_rn(
                            a0 + b_pe[col], a1 + b_pe[col + 1]);
                    } else if (kind == 2) {
                        *reinterpret_cast<__half2*>(z0h + off) = __floats2half2_rn(
                            a0 + b_hi[col], a1 + b_hi[col + 1]);
                    } else if (kind == 3) {
                        *reinterpret_cast<__half2*>(qh + off) = __floats2half2_rn(
                            a0 + cv[col], a1 + cv[col + 1]);
                    } else if (kind == 4) {
                        *reinterpret_cast<float2*>(y + off) = make_float2(a0, a1);
                        float2 qe = __half22float2(
                            *reinterpret_cast<const __half2*>(qh + off));
                        float u0 = tanh_ap(a0 + dt * qe.x + b1t[col]);
                        float u1 = tanh_ap(a1 + dt * qe.y + b1t[col + 1]);
                        *reinterpret_cast<__half2*>(uh + off) =
                            __floats2half2_rn(u0, u1);
                        *reinterpret_cast<float2*>(S + off) = make_float2(u0, u1);
                    } else if (kind == 5) {
                        const float tcoef = dt * (float)(gidx + 2);
                        float2 yv = __ldcg(reinterpret_cast<const float2*>(y + off));
                        float y0 = yv.x + dt * a0;
                        float y1 = yv.y + dt * a1;
                        *reinterpret_cast<float2*>(y + off) = make_float2(y0, y1);
                        float2 qe = __half22float2(
                            *reinterpret_cast<const __half2*>(qh + off));
                        float u0 = tanh_ap(y0 + tcoef * qe.x + b1t[col]);
                        float u1 = tanh_ap(y1 + tcoef * qe.y + b1t[col + 1]);
                        *reinterpret_cast<__half2*>(uh + off) =
                            __floats2half2_rn(u0, u1);
                        float2 Sv = __ldcg(reinterpret_cast<const float2*>(S + off));
                        Sv.x += u0; Sv.y += u1;
                        *reinterpret_cast<float2*>(S + off) = Sv;
                        if (gidx == NCHAIN - 1)
                            *reinterpret_cast<__half2*>(Sh + off) =
                                __floats2half2_rn(Sv.x, Sv.y);
                    } else if (kind == 6) {
                        *reinterpret_cast<__half2*>(w2ro + off) =
                            __floats2half2_rn(a0, a1);
                    } else if (kind == 7) {
                        *reinterpret_cast<float2*>(o1 + off) = make_float2(a0, a1);
                    } else {
                        float2 ov = __ldcg(reinterpret_cast<const float2*>(o1 + off));
                        *reinterpret_cast<float2*>(out + off) = make_float2(
                            ov.x + dt * a0 + b2ro[col],
                            ov.y + dt * a1 + b2ro[col + 1]);
                    }
                }
            }

        if (kind != 8) {
            __threadfence();
            __syncthreads();
            if (tid == 0) {
                if (kind == 0)      atomicAdd(&g_cw21, 1u);
                else if (kind == 6) atomicAdd(&g_cw2ro, 1u);
                else {
                    int ci = (kind == 1) ? 0 : (kind == 2) ? 1 : (kind == 3) ? 2
                           : (kind == 4) ? 3 : (kind == 5) ? (4 + gidx) : 53;
                    atomicAdd(&g_done[ci][bm], 1u);
                }
            }
        }
    }
}

// ---------------------------------------------------------------------------
// prep kernels (memory-bound, tiny)
// ---------------------------------------------------------------------------
__global__ void zero_sync()
{
    int i = blockIdx.x * blockDim.x + threadIdx.x;
    unsigned int* p = &g_done[0][0];
    int n = NCTR * ROWB;
    if (i < n) p[i] = 0;
    if (i == n)     g_tile_ctr = 0;
    if (i == n + 1) g_cw21 = 0;
    if (i == n + 2) g_cw2ro = 0;
}

__global__ void transpose_h16(const float* __restrict__ in, __half* __restrict__ out,
                              int K, int N)
{
    __shared__ float t[32][33];
    const int k0 = blockIdx.y * 32, n0 = blockIdx.x * 32;
    const int x = threadIdx.x, y = threadIdx.y;
#pragma unroll
    for (int i = 0; i < 32; i += 8)
        t[y + i][x] = in[(size_t)(k0 + y + i) * N + n0 + x];
    __syncthreads();
#pragma unroll
    for (int i = 0; i < 32; i += 8)
        out[(size_t)(n0 + y + i) * K + k0 + x] = __float2half_rn(t[x][y + i]);
}

__global__ void to_h16(const float4* __restrict__ in, __half2* __restrict__ out, int n4)
{
    int i = blockIdx.x * blockDim.x + threadIdx.x;
    if (i < n4) {
        float4 v = in[i];
        out[i * 2 + 0] = __floats2half2_rn(v.x, v.y);
        out[i * 2 + 1] = __floats2half2_rn(v.z, v.w);
    }
}

__global__ void vecmat_h16(const __half* __restrict__ Wt,
                           const float* __restrict__ vec,
                           const float* __restrict__ add,
                           float* __restrict__ outv)
{
    __shared__ float red[256];
    int n = blockIdx.x;
    float s = 0.f;
    for (int j = threadIdx.x; j < HID; j += 256)
        s += vec[j] * __half2float(Wt[(size_t)n * HID + j]);
    red[threadIdx.x] = s;
    __syncthreads();
    for (int k = 128; k > 0; k >>= 1) {
        if (threadIdx.x < k) red[threadIdx.x] += red[threadIdx.x + k];
        __syncthreads();
    }
    if (threadIdx.x == 0) outv[n] = red[0] + (add ? add[n] : 0.f);
}

__global__ void make_b1t(const float* __restrict__ b1, const float* __restrict__ cv,
                         float* __restrict__ b1t, float dt)
{
    int i = threadIdx.x + blockIdx.x * blockDim.x;
    if (i < HID) b1t[i] = b1[i] - dt * cv[i];
}

extern "C" void kernel_launch(void* const* d_in, const int* in_sizes, int n_in,
                              void* d_out, int out_size)
{
    const float* x0   = (const float*)d_in[0];
    const float* W_pe = (const float*)d_in[1];
    const float* b_pe = (const float*)d_in[2];
    const float* W_hi = (const float*)d_in[3];
    const float* b_hi = (const float*)d_in[4];
    const float* W1   = (const float*)d_in[5];
    const float* b1   = (const float*)d_in[6];
    const float* W2   = (const float*)d_in[7];
    const float* b2   = (const float*)d_in[8];
    const float* W_ro = (const float*)d_in[9];
    const float* b_ro = (const float*)d_in[10];
    float* out = (float*)d_out;

    __half *x0h, *gh, *qh, *z0h, *uh, *Shp;
    __half *wpe, *whi, *w1a, *w1b, *wro, *w2h, *w21, *w2ro;
    float *y, *S, *o1, *cv, *b1t, *b2ro;
    cudaGetSymbolAddress((void**)&x0h, x0h_buf);
    cudaGetSymbolAddress((void**)&gh,  gh_buf);
    cudaGetSymbolAddress((void**)&qh,  qh_buf);
    cudaGetSymbolAddress((void**)&z0h, z0h_buf);
    cudaGetSymbolAddress((void**)&uh,  uh_buf);
    cudaGetSymbolAddress((void**)&Shp, Sh_buf);
    cudaGetSymbolAddress((void**)&y,   y_buf);
    cudaGetSymbolAddress((void**)&S,   S_buf);
    cudaGetSymbolAddress((void**)&o1,  o1_buf);
    cudaGetSymbolAddress((void**)&wpe, WpeT);
    cudaGetSymbolAddress((void**)&whi, WhiT);
    cudaGetSymbolAddress((void**)&w1a, W1aT);
    cudaGetSymbolAddress((void**)&w1b, W1bT);
    cudaGetSymbolAddress((void**)&wro, WroT);
    cudaGetSymbolAddress((void**)&w2h, W2h);
    cudaGetSymbolAddress((void**)&w21, W21T_b);
    cudaGetSymbolAddress((void**)&w2ro, W2roT_b);
    cudaGetSymbolAddress((void**)&cv,  cvec_b);
    cudaGetSymbolAddress((void**)&b1t, b1t_b);
    cudaGetSymbolAddress((void**)&b2ro, b2ro_b);

    const float dt = 1.0f / (float)NSTEP;
    dim3 tb32(32, 8);

    int nthr = NCTR * ROWB + 3;
    zero_sync<<<(nthr + 255) / 256, 256>>>();

    transpose_h16<<<dim3(PATHD/32, DIN/32), tb32>>>(W_pe, wpe, DIN, PATHD);
    transpose_h16<<<dim3(HID/32,   DIN/32), tb32>>>(W_hi, whi, DIN, HID);
    transpose_h16<<<dim3(HID/32,   HID/32), tb32>>>(W1,   w1a, HID, HID);
    transpose_h16<<<dim3(HID/32,   PATHD/32), tb32>>>(W1 + (size_t)HID * HID, w1b, PATHD, HID);
    transpose_h16<<<dim3(HID/32,   HID/32), tb32>>>(W_ro, wro, HID, HID);

    int n4 = (BATCH * DIN) / 4;
    to_h16<<<(n4 + 255) / 256, 256>>>((const float4*)x0, (__half2*)x0h, n4);
    int w4 = (HID * HID) / 4;
    to_h16<<<(w4 + 255) / 256, 256>>>((const float4*)W2, (__half2*)w2h, w4);

    vecmat_h16<<<HID, 256>>>(w1a, b2, nullptr, cv);   // c = b2@W1a
    vecmat_h16<<<HID, 256>>>(wro, b2, b_ro, b2ro);    // b2ro = b2@Wro + b_ro
    make_b1t<<<4, 256>>>(b1, cv, b1t, dt);

    int dev = 0, nsm = 148;
    cudaGetDevice(&dev);
    cudaDeviceGetAttribute(&nsm, cudaDevAttrMultiProcessorCount, dev);
    cudaFuncSetAttribute(cde_all,
                         cudaFuncAttributeMaxDynamicSharedMemorySize, SMEM_BYTES);
    cde_all<<<2 * nsm, NTHREADS, SMEM_BYTES>>>(
        x0h, wpe, whi, w1a, w1b, wro, w2h, w21, w2ro,
        gh, qh, z0h, uh, Shp, y, S, o1, out,
        b_pe, b_hi, cv, b1t, b2ro, dt);
}

// round 11
// speedup vs baseline: 1.1220x; 1.1220x over previous
#include <cuda_runtime.h>
#include <cuda_fp16.h>
#include <cstdint>

// ---------------------------------------------------------------------------
// NeuralCDE rollout (R9 structure + merged independent prologue + y0 folded).
//   launch A (768 tiles, all independent): W21=(W2@W1a)^T, W2ro=(W2@Wro)^T,
//       g=h16(x0@Wpe+b_pe), z0h=h16(x0@Whi+b_hi)
//   launch B: q2 = h16(g@W1b + c)
//   launch C (persistent): y0: w=z0@W1a, u=tanh(w+dt q2+b1t), S=u
//       49x chain: w += dt u@W21 ; u = tanh(w + t q2 + b1t) ; S += u
//       o1 = z0@Wro (dep-free, fills tail) ; out = o1 + dt S@W2ro + b2ro
// ---------------------------------------------------------------------------

static constexpr int BATCH = 8192;
static constexpr int DIN   = 1024;
static constexpr int PATHD = 256;
static constexpr int HID   = 1024;
static constexpr int NSTEP = 50;
static constexpr int NCHAIN = NSTEP - 1;               // 49
static constexpr int ROWB  = BATCH / 128;              // 64

// persistent-kernel slots
static constexpr int S_Y0  = 0;                        // 512
static constexpr int S_CH  = S_Y0 + 512;               // 49*512
static constexpr int S_O1  = S_CH + NCHAIN * 512;      // 512
static constexpr int S_FIN = S_O1 + 512;               // 512
static constexpr int S_END = S_FIN + 512;
// counters: 0=y0, 1..49=chain gidx 0..48, 50=o1
static constexpr int NCTR  = 51;

// ---------------- device scratch ----------------
__device__ __half x0h_buf[(size_t)BATCH * DIN];
__device__ __half gh_buf [(size_t)BATCH * PATHD];
__device__ __half qh_buf [(size_t)BATCH * HID];
__device__ __half z0h_buf[(size_t)BATCH * HID];
__device__ __half uh_buf [(size_t)BATCH * HID];
__device__ __half Sh_buf [(size_t)BATCH * HID];
__device__ float  y_buf  [(size_t)BATCH * HID];
__device__ float  S_buf  [(size_t)BATCH * HID];
__device__ float  o1_buf [(size_t)BATCH * HID];
__device__ __half WpeT  [(size_t)PATHD * DIN];
__device__ __half WhiT  [(size_t)HID * DIN];
__device__ __half W1aT  [(size_t)HID * HID];
__device__ __half W1bT  [(size_t)HID * PATHD];
__device__ __half WroT  [(size_t)HID * HID];
__device__ __half W2h   [(size_t)HID * HID];
__device__ __half W21T_b[(size_t)HID * HID];
__device__ __half W2roT_b[(size_t)HID * HID];
__device__ float  cvec_b[HID];
__device__ float  b1t_b [HID];
__device__ float  b2ro_b[HID];

__device__ unsigned int g_done[NCTR][ROWB];
__device__ unsigned int g_tile_ctr;

// ---------------- tile configuration ----------------
static constexpr int BM = 128, BN = 128, BK = 32;
static constexpr int STAGES = 4, NTHREADS = 256;
static constexpr int STR  = BK + 8;
static constexpr int ASZ  = BM * STR;
static constexpr int BSZ  = BN * STR;
static constexpr int SMEM_BYTES = STAGES * (ASZ + BSZ) * 2; // 81920

__device__ __forceinline__ void ldmx4(uint32_t& r0, uint32_t& r1,
                                      uint32_t& r2, uint32_t& r3, uint32_t a) {
    asm volatile("ldmatrix.sync.aligned.m8n8.x4.shared.b16 {%0,%1,%2,%3}, [%4];"
                 : "=r"(r0), "=r"(r1), "=r"(r2), "=r"(r3) : "r"(a));
}
__device__ __forceinline__ float tanh_ap(float x) {
    float y;
    asm("tanh.approx.f32 %0, %1;" : "=f"(y) : "f"(x));
    return y;
}
__device__ __forceinline__ void spin_ge(volatile unsigned int* c, unsigned int v) {
    while (*c < v) __nanosleep(64);
}

// acc = A[bm*128.., :K] @ B[bn*128.., :K]^T
__device__ __forceinline__ void mainloop_f16(
    const __half* __restrict__ A, const __half* __restrict__ Bw,
    int K, int bm, int bn, __half* As, __half* Bs,
    float (&acc)[4][4][4])
{
    const int tid  = threadIdx.x;
    const int wid  = tid >> 5, lane = tid & 31;
    const int warp_m = wid & 1, warp_n = wid >> 1;
    const int KT = K / BK;

#pragma unroll
    for (int a = 0; a < 4; ++a)
#pragma unroll
        for (int b = 0; b < 4; ++b)
#pragma unroll
            for (int c = 0; c < 4; ++c) acc[a][b][c] = 0.f;

    auto load_tile = [&](int kt, int stage) {
        const __half* Ag = A + (size_t)(bm * BM) * K + (size_t)kt * BK;
        __half* Asb = As + stage * ASZ;
#pragma unroll
        for (int i = 0; i < 2; ++i) {
            int lin = i * NTHREADS + tid;
            int r = lin >> 2, c = (lin & 3) << 3;
            uint32_t sa = (uint32_t)__cvta_generic_to_shared(Asb + r * STR + c);
            asm volatile("cp.async.cg.shared.global [%0], [%1], 16;"
                         :: "r"(sa), "l"(Ag + (size_t)r * K + c));
        }
        const __half* Bg = Bw + (size_t)(bn * BN) * K + (size_t)kt * BK;
        __half* Bsb = Bs + stage * BSZ;
#pragma unroll
        for (int i = 0; i < 2; ++i) {
            int lin = i * NTHREADS + tid;
            int r = lin >> 2, c = (lin & 3) << 3;
            uint32_t sa = (uint32_t)__cvta_generic_to_shared(Bsb + r * STR + c);
            asm volatile("cp.async.cg.shared.global [%0], [%1], 16;"
                         :: "r"(sa), "l"(Bg + (size_t)r * K + c));
        }
        asm volatile("cp.async.commit_group;");
    };

    const int a_row  = warp_m * 64 + (lane & 15);
    const int a_koff = (lane >> 4) << 3;
    const int b_row  = warp_n * 32 + (lane & 7) + ((lane >> 4) << 3);
    const int b_koff = ((lane >> 3) & 1) << 3;

    for (int s = 0; s < STAGES - 1 && s < KT; ++s) load_tile(s, s);

    for (int kt = 0; kt < KT; ++kt) {
        if (kt < KT - (STAGES - 1))
            asm volatile("cp.async.wait_group %0;" :: "n"(STAGES - 2));
        else
            asm volatile("cp.async.wait_group 0;");
        __syncthreads();

        int pf = kt + STAGES - 1;
        if (pf < KT) load_tile(pf, pf % STAGES);

        const __half* Asb = As + (kt % STAGES) * ASZ;
        const __half* Bsb = Bs + (kt % STAGES) * BSZ;
        const uint32_t a_base = (uint32_t)__cvta_generic_to_shared(
            Asb + (size_t)a_row * STR + a_koff);
        const uint32_t b_base = (uint32_t)__cvta_generic_to_shared(
            Bsb + (size_t)b_row * STR + b_koff);

#pragma unroll
        for (int ks = 0; ks < BK / 16; ++ks) {
            uint32_t af[4][4], bf[4][2];
#pragma unroll
            for (int mi = 0; mi < 4; ++mi)
                ldmx4(af[mi][0], af[mi][1], af[mi][2], af[mi][3],
                      a_base + (mi * 16 * STR + ks * 16) * 2);
#pragma unroll
            for (int np = 0; np < 2; ++np)
                ldmx4(bf[np*2][0], bf[np*2][1], bf[np*2+1][0], bf[np*2+1][1],
                      b_base + (np * 16 * STR + ks * 16) * 2);
#pragma unroll
            for (int mi = 0; mi < 4; ++mi)
#pragma unroll
                for (int ni = 0; ni < 4; ++ni) {
                    asm volatile(
                        "mma.sync.aligned.m16n8k16.row.col.f32.f16.f16.f32 "
                        "{%0,%1,%2,%3}, {%4,%5,%6,%7}, {%8,%9}, {%0,%1,%2,%3};"
                        : "+f"(acc[mi][ni][0]), "+f"(acc[mi][ni][1]),
                          "+f"(acc[mi][ni][2]), "+f"(acc[mi][ni][3])
                        : "r"(af[mi][0]), "r"(af[mi][1]), "r"(af[mi][2]), "r"(af[mi][3]),
                          "r"(bf[ni][0]), "r"(bf[ni][1]));
                }
        }
    }
}

// ---------------------------------------------------------------------------
// launch A: merged independent prologue GEMMs (768 one-tile blocks)
//   blk 0..63    W21  = h16(W1a^T @ W2^T)      (A=w1aT, B=w2h)
//   blk 64..127  W2ro = h16(Wro^T @ W2^T)      (A=wroT, B=w2h)
//   blk 128..255 g    = h16(x0@Wpe + b_pe)
//   blk 256..767 z0h  = h16(x0@Whi + b_hi)
// ---------------------------------------------------------------------------
__global__ __launch_bounds__(NTHREADS, 2)
void gemm_indep(const __half* __restrict__ x0h,
                const __half* __restrict__ wpe, const __half* __restrict__ whi,
                const __half* __restrict__ w1a, const __half* __restrict__ wro,
                const __half* __restrict__ w2h,
                __half* __restrict__ w21, __half* __restrict__ w2ro,
                __half* __restrict__ gh, __half* __restrict__ z0h,
                const float* __restrict__ b_pe, const float* __restrict__ b_hi)
{
    extern __shared__ __half smem[];
    __half* As = smem;
    __half* Bs = smem + STAGES * ASZ;

    const int v = blockIdx.x;
    const __half* A;
    const __half* Bw;
    __half* C;
    const float* bias = nullptr;
    int K = HID, N = HID, bm, bn;

    if (v < 64)        { A = w1a; Bw = w2h; C = w21;  bm = v >> 3; bn = v & 7; }
    else if (v < 128)  { A = wro; Bw = w2h; C = w2ro; int t = v - 64; bm = t >> 3; bn = t & 7; }
    else if (v < 256)  { A = x0h; Bw = wpe; C = gh; bias = b_pe; K = DIN; N = PATHD;
                         int t = v - 128; bm = t >> 1; bn = t & 1; }
    else               { A = x0h; Bw = whi; C = z0h; bias = b_hi; K = DIN;
                         int t = v - 256; bm = t >> 3; bn = t & 7; }

    float acc[4][4][4];
    mainloop_f16(A, Bw, K, bm, bn, As, Bs, acc);

    const int tid = threadIdx.x, wid = tid >> 5, lane = tid & 31;
    const int gid = lane >> 2, tig = lane & 3;
    const int rbase = bm * BM + (wid & 1) * 64;
    const int cbase = bn * BN + (wid >> 1) * 32;
#pragma unroll
    for (int mi = 0; mi < 4; ++mi)
#pragma unroll
        for (int h2 = 0; h2 < 2; ++h2) {
            int row = rbase + mi * 16 + h2 * 8 + gid;
#pragma unroll
            for (int ni = 0; ni < 4; ++ni) {
                int col = cbase + ni * 8 + tig * 2;
                size_t off = (size_t)row * N + col;
                float v0 = acc[mi][ni][h2 * 2 + 0];
                float v1 = acc[mi][ni][h2 * 2 + 1];
                if (bias) { v0 += bias[col]; v1 += bias[col + 1]; }
                *reinterpret_cast<__half2*>(C + off) = __floats2half2_rn(v0, v1);
            }
        }
}

// ---------------------------------------------------------------------------
// launch B: q2 = h16(g @ W1b + c)
// ---------------------------------------------------------------------------
__global__ __launch_bounds__(NTHREADS, 2)
void gemm_q(const __half* __restrict__ gh, const __half* __restrict__ w1b,
            __half* __restrict__ qh, const float* __restrict__ cv)
{
    extern __shared__ __half smem[];
    __half* As = smem;
    __half* Bs = smem + STAGES * ASZ;
    float acc[4][4][4];
    mainloop_f16(gh, w1b, PATHD, blockIdx.y, blockIdx.x, As, Bs, acc);

    const int tid = threadIdx.x, wid = tid >> 5, lane = tid & 31;
    const int gid = lane >> 2, tig = lane & 3;
    const int rbase = blockIdx.y * BM + (wid & 1) * 64;
    const int cbase = blockIdx.x * BN + (wid >> 1) * 32;
#pragma unroll
    for (int mi = 0; mi < 4; ++mi)
#pragma unroll
        for (int h2 = 0; h2 < 2; ++h2) {
            int row = rbase + mi * 16 + h2 * 8 + gid;
#pragma unroll
            for (int ni = 0; ni < 4; ++ni) {
                int col = cbase + ni * 8 + tig * 2;
                size_t off = (size_t)row * HID + col;
                *reinterpret_cast<__half2*>(qh + off) = __floats2half2_rn(
                    acc[mi][ni][h2 * 2 + 0] + cv[col],
                    acc[mi][ni][h2 * 2 + 1] + cv[col + 1]);
            }
        }
}

// ---------------------------------------------------------------------------
// launch C: persistent — y0, 49 chain steps, o1, final
// ---------------------------------------------------------------------------
__global__ __launch_bounds__(NTHREADS, 2)
void cde_chain(const __half* __restrict__ W21, const __half* __restrict__ wro,
               const __half* __restrict__ w2ro, const __half* __restrict__ w1a,
               const __half* __restrict__ z0h, __half* __restrict__ uh,
               __half* __restrict__ Sh,
               float* __restrict__ y, float* __restrict__ S,
               float* __restrict__ o1, float* __restrict__ out,
               const __half* __restrict__ qh,
               const float* __restrict__ b1t, const float* __restrict__ b2ro,
               float dt)
{
    extern __shared__ __half smem[];
    __half* As = smem;
    __half* Bs = smem + STAGES * ASZ;
    __shared__ unsigned int s_tile;

    const int tid = threadIdx.x, wid = tid >> 5, lane = tid & 31;
    const int gid = lane >> 2, tig = lane & 3;

    while (true) {
        if (tid == 0) s_tile = atomicAdd(&g_tile_ctr, 1u);
        __syncthreads();
        const unsigned int v = s_tile;
        if (v >= (unsigned)S_END) break;

        int kind, gidx = 0, t;
        if (v < (unsigned)S_CH)       { kind = 0; t = v; }                       // y0
        else if (v < (unsigned)S_O1)  { kind = 1; gidx = (v - S_CH) >> 9; t = (v - S_CH) & 511; }
        else if (v < (unsigned)S_FIN) { kind = 2; t = v - S_O1; }                // o1
        else                          { kind = 3; t = v - S_FIN; }               // final
        const int bm = t >> 3, bn = t & 7;

        // dependencies
        if (tid == 0) {
            if (kind == 1) {
                spin_ge(&g_done[gidx][bm], 8u);     // y0 ctr=0, chain g-1 ctr=g
            } else if (kind == 3) {
                spin_ge(&g_done[NCHAIN][bm], 8u);   // last chain row
                spin_ge(&g_done[NCHAIN + 1][bm], 8u); // o1 row
            }
            __threadfence();
        }
        __syncthreads();

        const __half* A;
        const __half* Bw;
        if (kind == 0)      { A = z0h; Bw = w1a; }
        else if (kind == 1) { A = uh;  Bw = W21; }
        else if (kind == 2) { A = z0h; Bw = wro; }
        else                { A = Sh;  Bw = w2ro; }

        float acc[4][4][4];
        mainloop_f16(A, Bw, HID, bm, bn, As, Bs, acc);

        const int rbase = bm * BM + (wid & 1) * 64;
        const int cbase = bn * BN + (wid >> 1) * 32;

#pragma unroll
        for (int mi = 0; mi < 4; ++mi)
#pragma unroll
            for (int h2 = 0; h2 < 2; ++h2) {
                int row = rbase + mi * 16 + h2 * 8 + gid;
#pragma unroll
                for (int ni = 0; ni < 4; ++ni) {
                    int col = cbase + ni * 8 + tig * 2;
                    size_t off = (size_t)row * HID + col;
                    float a0 = acc[mi][ni][h2 * 2 + 0];
                    float a1 = acc[mi][ni][h2 * 2 + 1];

                    if (kind == 0) {
                        *reinterpret_cast<float2*>(y + off) = make_float2(a0, a1);
                        float2 qe = __half22float2(
                            *reinterpret_cast<const __half2*>(qh + off));
                        float u0 = tanh_ap(a0 + dt * qe.x + b1t[col]);
                        float u1 = tanh_ap(a1 + dt * qe.y + b1t[col + 1]);
                        *reinterpret_cast<__half2*>(uh + off) =
                            __floats2half2_rn(u0, u1);
                        *reinterpret_cast<float2*>(S + off) = make_float2(u0, u1);
                    } else if (kind == 1) {
                        const float tcoef = dt * (float)(gidx + 2);
                        float2 yv = __ldcg(reinterpret_cast<const float2*>(y + off));
                        float y0 = yv.x + dt * a0;
                        float y1 = yv.y + dt * a1;
                        *reinterpret_cast<float2*>(y + off) = make_float2(y0, y1);
                        float2 qe = __half22float2(
                            *reinterpret_cast<const __half2*>(qh + off));
                        float u0 = tanh_ap(y0 + tcoef * qe.x + b1t[col]);
                        float u1 = tanh_ap(y1 + tcoef * qe.y + b1t[col + 1]);
                        *reinterpret_cast<__half2*>(uh + off) =
                            __floats2half2_rn(u0, u1);
                        float2 Sv = __ldcg(reinterpret_cast<const float2*>(S + off));
                        Sv.x += u0; Sv.y += u1;
                        *reinterpret_cast<float2*>(S + off) = Sv;
                        if (gidx == NCHAIN - 1)
                            *reinterpret_cast<__half2*>(Sh + off) =
                                __floats2half2_rn(Sv.x, Sv.y);
                    } else if (kind == 2) {
                        *reinterpret_cast<float2*>(o1 + off) = make_float2(a0, a1);
                    } else {
                        float2 ov = __ldcg(reinterpret_cast<const float2*>(o1 + off));
                        *reinterpret_cast<float2*>(out + off) = make_float2(
                            ov.x + dt * a0 + b2ro[col],
                            ov.y + dt * a1 + b2ro[col + 1]);
                    }
                }
            }

        if (kind != 3) {
            __threadfence();
            __syncthreads();
            if (tid == 0) {
                int ci = (kind == 0) ? 0 : (kind == 1) ? (1 + gidx) : (NCHAIN + 1);
                atomicAdd(&g_done[ci][bm], 1u);
            }
        }
    }
}

// ---------------------------------------------------------------------------
// prep kernels
// ---------------------------------------------------------------------------
__global__ void zero_sync()
{
    int i = blockIdx.x * blockDim.x + threadIdx.x;
    unsigned int* p = &g_done[0][0];
    int n = NCTR * ROWB;
    if (i < n) p[i] = 0;
    if (i == n) g_tile_ctr = 0;
}

__global__ void transpose_h16(const float* __restrict__ in, __half* __restrict__ out,
                              int K, int N)
{
    __shared__ float t[32][33];
    const int k0 = blockIdx.y * 32, n0 = blockIdx.x * 32;
    const int x = threadIdx.x, y = threadIdx.y;
#pragma unroll
    for (int i = 0; i < 32; i += 8)
        t[y + i][x] = in[(size_t)(k0 + y + i) * N + n0 + x];
    __syncthreads();
#pragma unroll
    for (int i = 0; i < 32; i += 8)
        out[(size_t)(n0 + y + i) * K + k0 + x] = __float2half_rn(t[x][y + i]);
}

__global__ void to_h16(const float4* __restrict__ in, __half2* __restrict__ out, int n4)
{
    int i = blockIdx.x * blockDim.x + threadIdx.x;
    if (i < n4) {
        float4 v = in[i];
        out[i * 2 + 0] = __floats2half2_rn(v.x, v.y);
        out[i * 2 + 1] = __floats2half2_rn(v.z, v.w);
    }
}

__global__ void vecmat_h16(const __half* __restrict__ Wt,
                           const float* __restrict__ vec,
                           const float* __restrict__ add,
                           float* __restrict__ outv)
{
    __shared__ float red[256];
    int n = blockIdx.x;
    float s = 0.f;
    for (int j = threadIdx.x; j < HID; j += 256)
        s += vec[j] * __half2float(Wt[(size_t)n * HID + j]);
    red[threadIdx.x] = s;
    __syncthreads();
    for (int k = 128; k > 0; k >>= 1) {
        if (threadIdx.x < k) red[threadIdx.x] += red[threadIdx.x + k];
        __syncthreads();
    }
    if (threadIdx.x == 0) outv[n] = red[0] + (add ? add[n] : 0.f);
}

__global__ void make_b1t(const float* __restrict__ b1, const float* __restrict__ cv,
                         float* __restrict__ b1t, float dt)
{
    int i = threadIdx.x + blockIdx.x * blockDim.x;
    if (i < HID) b1t[i] = b1[i] - dt * cv[i];
}

extern "C" void kernel_launch(void* const* d_in, const int* in_sizes, int n_in,
                              void* d_out, int out_size)
{
    const float* x0   = (const float*)d_in[0];
    const float* W_pe = (const float*)d_in[1];
    const float* b_pe = (const float*)d_in[2];
    const float* W_hi = (const float*)d_in[3];
    const float* b_hi = (const float*)d_in[4];
    const float* W1   = (const float*)d_in[5];
    const float* b1   = (const float*)d_in[6];
    const float* W2   = (const float*)d_in[7];
    const float* b2   = (const float*)d_in[8];
    const float* W_ro = (const float*)d_in[9];
    const float* b_ro = (const float*)d_in[10];
    float* out = (float*)d_out;

    __half *x0h, *gh, *qh, *z0h, *uh, *Shp;
    __half *wpe, *whi, *w1a, *w1b, *wro, *w2h, *w21, *w2ro;
    float *y, *S, *o1, *cv, *b1t, *b2ro;
    cudaGetSymbolAddress((void**)&x0h, x0h_buf);
    cudaGetSymbolAddress((void**)&gh,  gh_buf);
    cudaGetSymbolAddress((void**)&qh,  qh_buf);
    cudaGetSymbolAddress((void**)&z0h, z0h_buf);
    cudaGetSymbolAddress((void**)&uh,  uh_buf);
    cudaGetSymbolAddress((void**)&Shp, Sh_buf);
    cudaGetSymbolAddress((void**)&y,   y_buf);
    cudaGetSymbolAddress((void**)&S,   S_buf);
    cudaGetSymbolAddress((void**)&o1,  o1_buf);
    cudaGetSymbolAddress((void**)&wpe, WpeT);
    cudaGetSymbolAddress((void**)&whi, WhiT);
    cudaGetSymbolAddress((void**)&w1a, W1aT);
    cudaGetSymbolAddress((void**)&w1b, W1bT);
    cudaGetSymbolAddress((void**)&wro, WroT);
    cudaGetSymbolAddress((void**)&w2h, W2h);
    cudaGetSymbolAddress((void**)&w21, W21T_b);
    cudaGetSymbolAddress((void**)&w2ro, W2roT_b);
    cudaGetSymbolAddress((void**)&cv,  cvec_b);
    cudaGetSymbolAddress((void**)&b1t, b1t_b);
    cudaGetSymbolAddress((void**)&b2ro, b2ro_b);

    const float dt = 1.0f / (float)NSTEP;
    dim3 tb32(32, 8);

    int nthr = NCTR * ROWB + 1;
    zero_sync<<<(nthr + 255) / 256, 256>>>();

    transpose_h16<<<dim3(PATHD/32, DIN/32), tb32>>>(W_pe, wpe, DIN, PATHD);
    transpose_h16<<<dim3(HID/32,   DIN/32), tb32>>>(W_hi, whi, DIN, HID);
    transpose_h16<<<dim3(HID/32,   HID/32), tb32>>>(W1,   w1a, HID, HID);
    transpose_h16<<<dim3(HID/32,   PATHD/32), tb32>>>(W1 + (size_t)HID * HID, w1b, PATHD, HID);
    transpose_h16<<<dim3(HID/32,   HID/32), tb32>>>(W_ro, wro, HID, HID);

    int n4 = (BATCH * DIN) / 4;
    to_h16<<<(n4 + 255) / 256, 256>>>((const float4*)x0, (__half2*)x0h, n4);
    int w4 = (HID * HID) / 4;
    to_h16<<<(w4 + 255) / 256, 256>>>((const float4*)W2, (__half2*)w2h, w4);

    vecmat_h16<<<HID, 256>>>(w1a, b2, nullptr, cv);   // c = b2@W1a
    vecmat_h16<<<HID, 256>>>(wro, b2, b_ro, b2ro);    // b2ro = b2@Wro + b_ro
    make_b1t<<<4, 256>>>(b1, cv, b1t, dt);

    // launch A: independent prologue (W21, W2ro, g, z0h) in one grid
    cudaFuncSetAttribute(gemm_indep,
                         cudaFuncAttributeMaxDynamicSharedMemorySize, SMEM_BYTES);
    gemm_indep<<<768, NTHREADS, SMEM_BYTES>>>(
        x0h, wpe, whi, w1a, wro, w2h, w21, w2ro, gh, z0h, b_pe, b_hi);

    // launch B: q2 = h16(g @ W1b + c)
    cudaFuncSetAttribute(gemm_q,
                         cudaFuncAttributeMaxDynamicSharedMemorySize, SMEM_BYTES);
    gemm_q<<<dim3(HID / BN, BATCH / BM), NTHREADS, SMEM_BYTES>>>(gh, w1b, qh, cv);

    // launch C: persistent y0 + chain + o1 + final
    int dev = 0, nsm = 148;
    cudaGetDevice(&dev);
    cudaDeviceGetAttribute(&nsm, cudaDevAttrMultiProcessorCount, dev);
    cudaFuncSetAttribute(cde_chain,
                         cudaFuncAttributeMaxDynamicSharedMemorySize, SMEM_BYTES);
    cde_chain<<<2 * nsm, NTHREADS, SMEM_BYTES>>>(
        w21, wro, w2ro, w1a, z0h, uh, Shp, y, S, o1, out, qh, b1t, b2ro, dt);
}

// round 12
// speedup vs baseline: 1.2392x; 1.1045x over previous
#include <cuda_runtime.h>
#include <cuda_fp16.h>
#include <cstdint>

// ---------------------------------------------------------------------------
// NeuralCDE rollout (R9 base): one GEMM per step, tail folded into the chain.
//   q2 = h16(x0@Wpe+b_pe)@W1b + c          (c = b2@W1a, drift transform)
//   z0h = h16(x0@Whi + b_hi)
//   w0 = z0@W1a ; u1 = tanh(w0 + t1 q2 + b1t) ; S = u1     (b1t = b1 - dt c)
//   49x: w += dt (u@W21) ; u = tanh(w + t q2 + b1t) ; S += u
//   o1  = z0@Wro ; out = o1 + dt (S@W2ro) + b2ro
// R12: u ping-pong slabs (fixes WAR race), y/S interleaved float4 stream.
// ---------------------------------------------------------------------------

static constexpr int BATCH = 8192;
static constexpr int DIN   = 1024;
static constexpr int PATHD = 256;
static constexpr int HID   = 1024;
static constexpr int NSTEP = 50;
static constexpr int NCHAIN = NSTEP - 1;               // 49
static constexpr int TPG   = (BATCH/128) * (HID/128);  // 512
static constexpr int SLOT_CHAIN = NCHAIN * TPG;        // 25088
static constexpr int SLOT_O1    = SLOT_CHAIN + TPG;    // 25600
static constexpr int SLOT_END   = SLOT_O1 + TPG;       // 26112
static constexpr int ROWB  = BATCH / 128;              // 64
static constexpr int NCTR  = NCHAIN + 1;               // chain 0..48, o1 = 49

// ---------------- device scratch ----------------
__device__ __half x0h_buf[(size_t)BATCH * DIN];
__device__ __half gh_buf [(size_t)BATCH * PATHD];
__device__ __half qh_buf [(size_t)BATCH * HID];       // q2 = q + c (fp16)
__device__ __half z0h_buf[(size_t)BATCH * HID];
__device__ __half u0_buf [(size_t)BATCH * HID];       // u slab parity 0
__device__ __half u1_buf [(size_t)BATCH * HID];       // u slab parity 1
__device__ __half Sh_buf [(size_t)BATCH * HID];
__device__ float  yS_buf [(size_t)BATCH * HID * 2];   // (y0,y1,S0,S1) per 2 cols
__device__ float  o1_buf [(size_t)BATCH * HID];
__device__ __half WpeT  [(size_t)PATHD * DIN];
__device__ __half WhiT  [(size_t)HID * DIN];
__device__ __half W1aT  [(size_t)HID * HID];
__device__ __half W1bT  [(size_t)HID * PATHD];
__device__ __half WroT  [(size_t)HID * HID];
__device__ __half W2h   [(size_t)HID * HID];
__device__ __half W21T_b[(size_t)HID * HID];
__device__ __half W2roT_b[(size_t)HID * HID];
__device__ float  cvec_b[HID];
__device__ float  b1t_b [HID];
__device__ float  b2ro_b[HID];
__device__ float  zero_bias[HID];

__device__ unsigned int g_done[NCTR][ROWB];
__device__ unsigned int g_tile_ctr;

// ---------------- tile configuration ----------------
static constexpr int BM = 128, BN = 128, BK = 32;
static constexpr int STAGES = 4, NTHREADS = 256;
static constexpr int STR  = BK + 8;
static constexpr int ASZ  = BM * STR;
static constexpr int BSZ  = BN * STR;
static constexpr int SMEM_BYTES = STAGES * (ASZ + BSZ) * 2; // 81920

__device__ __forceinline__ void ldmx4(uint32_t& r0, uint32_t& r1,
                                      uint32_t& r2, uint32_t& r3, uint32_t a) {
    asm volatile("ldmatrix.sync.aligned.m8n8.x4.shared.b16 {%0,%1,%2,%3}, [%4];"
                 : "=r"(r0), "=r"(r1), "=r"(r2), "=r"(r3) : "r"(a));
}
__device__ __forceinline__ float tanh_ap(float x) {
    float y;
    asm("tanh.approx.f32 %0, %1;" : "=f"(y) : "f"(x));
    return y;
}
__device__ __forceinline__ void spin_ge(volatile unsigned int* c, unsigned int v) {
    while (*c < v) __nanosleep(64);
}

// acc = A[bm*128.., :K] @ B[bn*128.., :K]^T
__device__ __forceinline__ void mainloop_f16(
    const __half* __restrict__ A, const __half* __restrict__ Bw,
    int K, int bm, int bn, __half* As, __half* Bs,
    float (&acc)[4][4][4])
{
    const int tid  = threadIdx.x;
    const int wid  = tid >> 5, lane = tid & 31;
    const int warp_m = wid & 1, warp_n = wid >> 1;
    const int KT = K / BK;

#pragma unroll
    for (int a = 0; a < 4; ++a)
#pragma unroll
        for (int b = 0; b < 4; ++b)
#pragma unroll
            for (int c = 0; c < 4; ++c) acc[a][b][c] = 0.f;

    auto load_tile = [&](int kt, int stage) {
        const __half* Ag = A + (size_t)(bm * BM) * K + (size_t)kt * BK;
        __half* Asb = As + stage * ASZ;
#pragma unroll
        for (int i = 0; i < 2; ++i) {
            int lin = i * NTHREADS + tid;
            int r = lin >> 2, c = (lin & 3) << 3;
            uint32_t sa = (uint32_t)__cvta_generic_to_shared(Asb + r * STR + c);
            asm volatile("cp.async.cg.shared.global [%0], [%1], 16;"
                         :: "r"(sa), "l"(Ag + (size_t)r * K + c));
        }
        const __half* Bg = Bw + (size_t)(bn * BN) * K + (size_t)kt * BK;
        __half* Bsb = Bs + stage * BSZ;
#pragma unroll
        for (int i = 0; i < 2; ++i) {
            int lin = i * NTHREADS + tid;
            int r = lin >> 2, c = (lin & 3) << 3;
            uint32_t sa = (uint32_t)__cvta_generic_to_shared(Bsb + r * STR + c);
            asm volatile("cp.async.cg.shared.global [%0], [%1], 16;"
                         :: "r"(sa), "l"(Bg + (size_t)r * K + c));
        }
        asm volatile("cp.async.commit_group;");
    };

    const int a_row  = warp_m * 64 + (lane & 15);
    const int a_koff = (lane >> 4) << 3;
    const int b_row  = warp_n * 32 + (lane & 7) + ((lane >> 4) << 3);
    const int b_koff = ((lane >> 3) & 1) << 3;

    for (int s = 0; s < STAGES - 1 && s < KT; ++s) load_tile(s, s);

    for (int kt = 0; kt < KT; ++kt) {
        if (kt < KT - (STAGES - 1))
            asm volatile("cp.async.wait_group %0;" :: "n"(STAGES - 2));
        else
            asm volatile("cp.async.wait_group 0;");
        __syncthreads();

        int pf = kt + STAGES - 1;
        if (pf < KT) load_tile(pf, pf % STAGES);

        const __half* Asb = As + (kt % STAGES) * ASZ;
        const __half* Bsb = Bs + (kt % STAGES) * BSZ;
        const uint32_t a_base = (uint32_t)__cvta_generic_to_shared(
            Asb + (size_t)a_row * STR + a_koff);
        const uint32_t b_base = (uint32_t)__cvta_generic_to_shared(
            Bsb + (size_t)b_row * STR + b_koff);

#pragma unroll
        for (int ks = 0; ks < BK / 16; ++ks) {
            uint32_t af[4][4], bf[4][2];
#pragma unroll
            for (int mi = 0; mi < 4; ++mi)
                ldmx4(af[mi][0], af[mi][1], af[mi][2], af[mi][3],
                      a_base + (mi * 16 * STR + ks * 16) * 2);
#pragma unroll
            for (int np = 0; np < 2; ++np)
                ldmx4(bf[np*2][0], bf[np*2][1], bf[np*2+1][0], bf[np*2+1][1],
                      b_base + (np * 16 * STR + ks * 16) * 2);
#pragma unroll
            for (int mi = 0; mi < 4; ++mi)
#pragma unroll
                for (int ni = 0; ni < 4; ++ni) {
                    asm volatile(
                        "mma.sync.aligned.m16n8k16.row.col.f32.f16.f16.f32 "
                        "{%0,%1,%2,%3}, {%4,%5,%6,%7}, {%8,%9}, {%0,%1,%2,%3};"
                        : "+f"(acc[mi][ni][0]), "+f"(acc[mi][ni][1]),
                          "+f"(acc[mi][ni][2]), "+f"(acc[mi][ni][3])
                        : "r"(af[mi][0]), "r"(af[mi][1]), "r"(af[mi][2]), "r"(af[mi][3]),
                          "r"(bf[ni][0]), "r"(bf[ni][1]));
                }
        }
    }
}

// ---------------------------------------------------------------------------
// prologue GEMM: Ch = h16(acc + bias)
// ---------------------------------------------------------------------------
__global__ __launch_bounds__(NTHREADS, 2)
void gemm_pre(const __half* __restrict__ A, const __half* __restrict__ Bw,
              __half* __restrict__ Ch, int N, int K,
              const float* __restrict__ bias)
{
    extern __shared__ __half smem[];
    __half* As = smem;
    __half* Bs = smem + STAGES * ASZ;
    float acc[4][4][4];
    mainloop_f16(A, Bw, K, blockIdx.y, blockIdx.x, As, Bs, acc);

    const int tid = threadIdx.x, wid = tid >> 5, lane = tid & 31;
    const int gid = lane >> 2, tig = lane & 3;
    const int rbase = blockIdx.y * BM + (wid & 1) * 64;
    const int cbase = blockIdx.x * BN + (wid >> 1) * 32;
#pragma unroll
    for (int mi = 0; mi < 4; ++mi)
#pragma unroll
        for (int h2 = 0; h2 < 2; ++h2) {
            int row = rbase + mi * 16 + h2 * 8 + gid;
#pragma unroll
            for (int ni = 0; ni < 4; ++ni) {
                int col = cbase + ni * 8 + tig * 2;
                size_t off = (size_t)row * N + col;
                *reinterpret_cast<__half2*>(Ch + off) = __floats2half2_rn(
                    acc[mi][ni][h2 * 2 + 0] + bias[col],
                    acc[mi][ni][h2 * 2 + 1] + bias[col + 1]);
            }
        }
}

// ---------------------------------------------------------------------------
// w0 = z0 @ W1a ; u1 = tanh(w0 + dt q2 + b1t) -> u slab1 ; yS = (w0, u1)
// ---------------------------------------------------------------------------
__global__ __launch_bounds__(NTHREADS, 2)
void gemm_y0(const __half* __restrict__ A, const __half* __restrict__ Bw,
             float* __restrict__ yS, __half* __restrict__ u1s,
             const __half* __restrict__ qh, const float* __restrict__ b1t,
             float dt)
{
    extern __shared__ __half smem[];
    __half* As = smem;
    __half* Bs = smem + STAGES * ASZ;
    float acc[4][4][4];
    mainloop_f16(A, Bw, HID, blockIdx.y, blockIdx.x, As, Bs, acc);

    const int tid = threadIdx.x, wid = tid >> 5, lane = tid & 31;
    const int gid = lane >> 2, tig = lane & 3;
    const int rbase = blockIdx.y * BM + (wid & 1) * 64;
    const int cbase = blockIdx.x * BN + (wid >> 1) * 32;
#pragma unroll
    for (int mi = 0; mi < 4; ++mi)
#pragma unroll
        for (int h2 = 0; h2 < 2; ++h2) {
            int row = rbase + mi * 16 + h2 * 8 + gid;
#pragma unroll
            for (int ni = 0; ni < 4; ++ni) {
                int col = cbase + ni * 8 + tig * 2;
                size_t uoff  = (size_t)row * HID + col;
                size_t ysoff = (size_t)row * (2 * HID) + col * 2;
                float a0 = acc[mi][ni][h2 * 2 + 0];
                float a1 = acc[mi][ni][h2 * 2 + 1];
                float2 qe = __half22float2(
                    *reinterpret_cast<const __half2*>(qh + uoff));
                float u0 = tanh_ap(a0 + dt * qe.x + b1t[col]);
                float u1 = tanh_ap(a1 + dt * qe.y + b1t[col + 1]);
                *reinterpret_cast<__half2*>(u1s + uoff) = __floats2half2_rn(u0, u1);
                *reinterpret_cast<float4*>(yS + ysoff) =
                    make_float4(a0, a1, u0, u1);
            }
        }
}

// ---------------------------------------------------------------------------
// persistent kernel: 49 chain GEMMs + o1 + final (tail folded)
// ---------------------------------------------------------------------------
__global__ __launch_bounds__(NTHREADS, 2)
void cde_chain(const __half* __restrict__ W21, const __half* __restrict__ wro,
               const __half* __restrict__ w2ro,
               const __half* __restrict__ z0h,
               __half* __restrict__ u0s, __half* __restrict__ u1s,
               __half* __restrict__ Sh,
               float* __restrict__ yS,
               float* __restrict__ o1, float* __restrict__ out,
               const __half* __restrict__ qh,
               const float* __restrict__ b1t, const float* __restrict__ b2ro,
               float dt)
{
    extern __shared__ __half smem[];
    __half* As = smem;
    __half* Bs = smem + STAGES * ASZ;
    __shared__ unsigned int s_tile;

    const int tid = threadIdx.x, wid = tid >> 5, lane = tid & 31;
    const int gid = lane >> 2, tig = lane & 3;

    while (true) {
        if (tid == 0) s_tile = atomicAdd(&g_tile_ctr, 1u);
        __syncthreads();
        unsigned int v = s_tile;
        if (v >= (unsigned)SLOT_END) break;

        int kind, gidx = 0, t;
        if (v < (unsigned)SLOT_CHAIN)      { kind = 0; gidx = v >> 9; t = v & 511; }
        else if (v < (unsigned)SLOT_O1)    { kind = 1; t = v - SLOT_CHAIN; }
        else                               { kind = 2; t = v - SLOT_O1; }
        const int bm = t >> 3, bn = t & 7;

        // dependencies
        if (tid == 0) {
            if (kind == 0 && gidx > 0) {
                spin_ge(&g_done[gidx - 1][bm], 8u);
                __threadfence();
            } else if (kind == 2) {
                spin_ge(&g_done[NCHAIN - 1][bm], 8u);
                spin_ge(&g_done[NCHAIN][bm], 8u);
                __threadfence();
            }
        }
        __syncthreads();

        // chain step gidx computes u_{gidx+2}: reads u slab (gidx+1)&1,
        // writes u slab gidx&1  (u_s lives in slab s&1; u1 from gemm_y0)
        const __half* A;
        const __half* Bw;
        if (kind == 0)      { A = ((gidx + 1) & 1) ? u1s : u0s; Bw = W21; }
        else if (kind == 1) { A = z0h; Bw = wro;  }
        else                { A = Sh;  Bw = w2ro; }

        float acc[4][4][4];
        mainloop_f16(A, Bw, HID, bm, bn, As, Bs, acc);

        const int rbase = bm * BM + (wid & 1) * 64;
        const int cbase = bn * BN + (wid >> 1) * 32;

        if (kind == 0) {
            __half* Cu = (gidx & 1) ? u1s : u0s;
            const float tcoef = dt * (float)(gidx + 2);
            const bool last = (gidx == NCHAIN - 1);
#pragma unroll
            for (int mi = 0; mi < 4; ++mi)
#pragma unroll
                for (int h2 = 0; h2 < 2; ++h2) {
                    int row = rbase + mi * 16 + h2 * 8 + gid;
#pragma unroll
                    for (int ni = 0; ni < 4; ++ni) {
                        int col = cbase + ni * 8 + tig * 2;
                        size_t uoff  = (size_t)row * HID + col;
                        size_t ysoff = (size_t)row * (2 * HID) + col * 2;
                        float a0 = acc[mi][ni][h2 * 2 + 0];
                        float a1 = acc[mi][ni][h2 * 2 + 1];
                        float4 ys = __ldcg(reinterpret_cast<const float4*>(yS + ysoff));
                        ys.x += dt * a0;
                        ys.y += dt * a1;
                        float2 qe = __half22float2(
                            *reinterpret_cast<const __half2*>(qh + uoff));
                        float u0 = tanh_ap(ys.x + tcoef * qe.x + b1t[col]);
                        float u1 = tanh_ap(ys.y + tcoef * qe.y + b1t[col + 1]);
                        ys.z += u0;
                        ys.w += u1;
                        *reinterpret_cast<__half2*>(Cu + uoff) =
                            __floats2half2_rn(u0, u1);
                        *reinterpret_cast<float4*>(yS + ysoff) = ys;
                        if (last)
                            *reinterpret_cast<__half2*>(Sh + uoff) =
                                __floats2half2_rn(ys.z, ys.w);
                    }
                }
        } else if (kind == 1) {
#pragma unroll
            for (int mi = 0; mi < 4; ++mi)
#pragma unroll
                for (int h2 = 0; h2 < 2; ++h2) {
                    int row = rbase + mi * 16 + h2 * 8 + gid;
#pragma unroll
                    for (int ni = 0; ni < 4; ++ni) {
                        int col = cbase + ni * 8 + tig * 2;
                        size_t off = (size_t)row * HID + col;
                        *reinterpret_cast<float2*>(o1 + off) = make_float2(
                            acc[mi][ni][h2 * 2 + 0], acc[mi][ni][h2 * 2 + 1]);
                    }
                }
        } else {
#pragma unroll
            for (int mi = 0; mi < 4; ++mi)
#pragma unroll
                for (int h2 = 0; h2 < 2; ++h2) {
                    int row = rbase + mi * 16 + h2 * 8 + gid;
#pragma unroll
                    for (int ni = 0; ni < 4; ++ni) {
                        int col = cbase + ni * 8 + tig * 2;
                        size_t off = (size_t)row * HID + col;
                        float2 ov = __ldcg(reinterpret_cast<const float2*>(o1 + off));
                        *reinterpret_cast<float2*>(out + off) = make_float2(
                            ov.x + dt * acc[mi][ni][h2 * 2 + 0] + b2ro[col],
                            ov.y + dt * acc[mi][ni][h2 * 2 + 1] + b2ro[col + 1]);
                    }
                }
        }

        if (kind != 2) {
            __threadfence();
            __syncthreads();
            if (tid == 0) {
                int ci = (kind == 0) ? gidx : NCHAIN;
                atomicAdd(&g_done[ci][bm], 1u);
            }
        }
    }
}

// ---------------------------------------------------------------------------
// prep kernels
// ---------------------------------------------------------------------------
__global__ void zero_sync()
{
    int i = blockIdx.x * blockDim.x + threadIdx.x;
    unsigned int* p = &g_done[0][0];
    int n = NCTR * ROWB;
    if (i < n) p[i] = 0;
    if (i == n) g_tile_ctr = 0;
}

__global__ void transpose_h16(const float* __restrict__ in, __half* __restrict__ out,
                              int K, int N)
{
    __shared__ float t[32][33];
    const int k0 = blockIdx.y * 32, n0 = blockIdx.x * 32;
    const int x = threadIdx.x, y = threadIdx.y;
#pragma unroll
    for (int i = 0; i < 32; i += 8)
        t[y + i][x] = in[(size_t)(k0 + y + i) * N + n0 + x];
    __syncthreads();
#pragma unroll
    for (int i = 0; i < 32; i += 8)
        out[(size_t)(n0 + y + i) * K + k0 + x] = __float2half_rn(t[x][y + i]);
}

__global__ void to_h16(const float4* __restrict__ in, __half2* __restrict__ out, int n4)
{
    int i = blockIdx.x * blockDim.x + threadIdx.x;
    if (i < n4) {
        float4 v = in[i];
        out[i * 2 + 0] = __floats2half2_rn(v.x, v.y);
        out[i * 2 + 1] = __floats2half2_rn(v.z, v.w);
    }
}

__global__ void vecmat_h16(const __half* __restrict__ Wt,
                           const float* __restrict__ vec,
                           const float* __restrict__ add,
                           float* __restrict__ outv)
{
    __shared__ float red[256];
    int n = blockIdx.x;
    float s = 0.f;
    for (int j = threadIdx.x; j < HID; j += 256)
        s += vec[j] * __half2float(Wt[(size_t)n * HID + j]);
    red[threadIdx.x] = s;
    __syncthreads();
    for (int k = 128; k > 0; k >>= 1) {
        if (threadIdx.x < k) red[threadIdx.x] += red[threadIdx.x + k];
        __syncthreads();
    }
    if (threadIdx.x == 0) outv[n] = red[0] + (add ? add[n] : 0.f);
}

__global__ void make_b1t(const float* __restrict__ b1, const float* __restrict__ cv,
                         float* __restrict__ b1t, float dt)
{
    int i = threadIdx.x + blockIdx.x * blockDim.x;
    if (i < HID) b1t[i] = b1[i] - dt * cv[i];
}

static void run_pre(const __half* A, const __half* Bw, __half* Ch,
                    int M, int N, int K, const float* bias)
{
    cudaFuncSetAttribute(gemm_pre,
                         cudaFuncAttributeMaxDynamicSharedMemorySize, SMEM_BYTES);
    dim3 grid(N / BN, M / BM);
    gemm_pre<<<grid, NTHREADS, SMEM_BYTES>>>(A, Bw, Ch, N, K, bias);
}

extern "C" void kernel_launch(void* const* d_in, const int* in_sizes, int n_in,
                              void* d_out, int out_size)
{
    const float* x0   = (const float*)d_in[0];
    const float* W_pe = (const float*)d_in[1];
    const float* b_pe = (const float*)d_in[2];
    const float* W_hi = (const float*)d_in[3];
    const float* b_hi = (const float*)d_in[4];
    const float* W1   = (const float*)d_in[5];
    const float* b1   = (const float*)d_in[6];
    const float* W2   = (const float*)d_in[7];
    const float* b2   = (const float*)d_in[8];
    const float* W_ro = (const float*)d_in[9];
    const float* b_ro = (const float*)d_in[10];
    float* out = (float*)d_out;

    __half *x0h, *gh, *qh, *z0h, *u0s, *u1s, *Shp;
    __half *wpe, *whi, *w1a, *w1b, *wro, *w2h, *w21, *w2ro;
    float *yS, *o1, *cv, *b1t, *b2ro, *zb;
    cudaGetSymbolAddress((void**)&x0h, x0h_buf);
    cudaGetSymbolAddress((void**)&gh,  gh_buf);
    cudaGetSymbolAddress((void**)&qh,  qh_buf);
    cudaGetSymbolAddress((void**)&z0h, z0h_buf);
    cudaGetSymbolAddress((void**)&u0s, u0_buf);
    cudaGetSymbolAddress((void**)&u1s, u1_buf);
    cudaGetSymbolAddress((void**)&Shp, Sh_buf);
    cudaGetSymbolAddress((void**)&yS,  yS_buf);
    cudaGetSymbolAddress((void**)&o1,  o1_buf);
    cudaGetSymbolAddress((void**)&wpe, WpeT);
    cudaGetSymbolAddress((void**)&whi, WhiT);
    cudaGetSymbolAddress((void**)&w1a, W1aT);
    cudaGetSymbolAddress((void**)&w1b, W1bT);
    cudaGetSymbolAddress((void**)&wro, WroT);
    cudaGetSymbolAddress((void**)&w2h, W2h);
    cudaGetSymbolAddress((void**)&w21, W21T_b);
    cudaGetSymbolAddress((void**)&w2ro, W2roT_b);
    cudaGetSymbolAddress((void**)&cv,  cvec_b);
    cudaGetSymbolAddress((void**)&b1t, b1t_b);
    cudaGetSymbolAddress((void**)&b2ro, b2ro_b);
    cudaGetSymbolAddress((void**)&zb,  zero_bias);

    const float dt = 1.0f / (float)NSTEP;
    dim3 tb32(32, 8);

    int nthr = NCTR * ROWB + 1;
    zero_sync<<<(nthr + 255) / 256, 256>>>();

    transpose_h16<<<dim3(PATHD/32, DIN/32), tb32>>>(W_pe, wpe, DIN, PATHD);
    transpose_h16<<<dim3(HID/32,   DIN/32), tb32>>>(W_hi, whi, DIN, HID);
    transpose_h16<<<dim3(HID/32,   HID/32), tb32>>>(W1,   w1a, HID, HID);
    transpose_h16<<<dim3(HID/32,   PATHD/32), tb32>>>(W1 + (size_t)HID * HID, w1b, PATHD, HID);
    transpose_h16<<<dim3(HID/32,   HID/32), tb32>>>(W_ro, wro, HID, HID);

    int n4 = (BATCH * DIN) / 4;
    to_h16<<<(n4 + 255) / 256, 256>>>((const float4*)x0, (__half2*)x0h, n4);
    int w4 = (HID * HID) / 4;
    to_h16<<<(w4 + 255) / 256, 256>>>((const float4*)W2, (__half2*)w2h, w4);

    // composed weights + vectors
    run_pre(w1a, w2h, w21,  HID, HID, HID, zb);   // W21T  = (W2@W1a)^T
    run_pre(wro, w2h, w2ro, HID, HID, HID, zb);   // W2roT = (W2@Wro)^T
    vecmat_h16<<<HID, 256>>>(w1a, b2, nullptr, cv);        // c = b2@W1a
    vecmat_h16<<<HID, 256>>>(wro, b2, b_ro, b2ro);         // b2ro = b2@Wro + b_ro
    make_b1t<<<4, 256>>>(b1, cv, b1t, dt);

    // activations: g, q2 = q + c (bias trick), z0h
    run_pre(x0h, wpe, gh, BATCH, PATHD, DIN, b_pe);
    run_pre(gh,  w1b, qh, BATCH, HID, PATHD, cv);          // q2
    run_pre(x0h, whi, z0h, BATCH, HID, DIN, b_hi);

    // w0 / u1 / S  (u1 -> slab 1)
    {
        cudaFuncSetAttribute(gemm_y0,
                             cudaFuncAttributeMaxDynamicSharedMemorySize, SMEM_BYTES);
        dim3 grid(HID / BN, BATCH / BM);
        gemm_y0<<<grid, NTHREADS, SMEM_BYTES>>>(z0h, w1a, yS, u1s, qh, b1t, dt);
    }

    // persistent chain + o1 + final
    int dev = 0, nsm = 148;
    cudaGetDevice(&dev);
    cudaDeviceGetAttribute(&nsm, cudaDevAttrMultiProcessorCount, dev);
    cudaFuncSetAttribute(cde_chain,
                         cudaFuncAttributeMaxDynamicSharedMemorySize, SMEM_BYTES);
    cde_chain<<<2 * nsm, NTHREADS, SMEM_BYTES>>>(
        w21, wro, w2ro, z0h, u0s, u1s, Shp, yS, o1, out, qh, b1t, b2ro, dt);
}

// round 13
// speedup vs baseline: 1.2650x; 1.0208x over previous
#include <cuda_runtime.h>
#include <cuda_fp16.h>
#include <cstdint>

// ---------------------------------------------------------------------------
// NeuralCDE rollout — R12 epilogues + fully pipelined persistent schedule.
//   launch A (768 indep tiles): W21=(W2@W1a)^T, W2ro=(W2@Wro)^T,
//       g=h16(x0@Wpe+b_pe), z0h=h16(x0@Whi+b_hi)
//   persistent: q2=h16(g@W1b+c)  [dep-free]
//       y0: w=z0@W1a, u1=tanh(w+dt q2+b1t), yS=(w,u1)   [dep: q row]
//       49x chain: w += dt u@W21 ; u = tanh(w + t q2 + b1t) ; S += u
//       o1 = z0@Wro [dep-free, tail filler] ; out = o1 + dt S@W2ro + b2ro
//   u ping-pong slabs; y/S interleaved float4 stream.
// ---------------------------------------------------------------------------

static constexpr int BATCH = 8192;
static constexpr int DIN   = 1024;
static constexpr int PATHD = 256;
static constexpr int HID   = 1024;
static constexpr int NSTEP = 50;
static constexpr int NCHAIN = NSTEP - 1;               // 49
static constexpr int TPG   = (BATCH/128) * (HID/128);  // 512
static constexpr int ROWB  = BATCH / 128;              // 64

// persistent slot layout
static constexpr int S_Q   = 0;                        // 512
static constexpr int S_Y0  = S_Q + TPG;                // 512
static constexpr int S_CH  = S_Y0 + TPG;               // 49*512
static constexpr int S_O1  = S_CH + NCHAIN * TPG;      // 512
static constexpr int S_FIN = S_O1 + TPG;               // 512
static constexpr int S_END = S_FIN + TPG;
// counters: 0=q, 1=y0, 2..50=chain 0..48, 51=o1
static constexpr int NCTR  = 52;

// ---------------- device scratch ----------------
__device__ __half x0h_buf[(size_t)BATCH * DIN];
__device__ __half gh_buf [(size_t)BATCH * PATHD];
__device__ __half qh_buf [(size_t)BATCH * HID];
__device__ __half z0h_buf[(size_t)BATCH * HID];
__device__ __half u0_buf [(size_t)BATCH * HID];
__device__ __half u1_buf [(size_t)BATCH * HID];
__device__ __half Sh_buf [(size_t)BATCH * HID];
__device__ float  yS_buf [(size_t)BATCH * HID * 2];   // (y0,y1,S0,S1) per 2 cols
__device__ float  o1_buf [(size_t)BATCH * HID];
__device__ __half WpeT  [(size_t)PATHD * DIN];
__device__ __half WhiT  [(size_t)HID * DIN];
__device__ __half W1aT  [(size_t)HID * HID];
__device__ __half W1bT  [(size_t)HID * PATHD];
__device__ __half WroT  [(size_t)HID * HID];
__device__ __half W2h   [(size_t)HID * HID];
__device__ __half W21T_b[(size_t)HID * HID];
__device__ __half W2roT_b[(size_t)HID * HID];
__device__ float  cvec_b[HID];
__device__ float  b1t_b [HID];
__device__ float  b2ro_b[HID];

__device__ unsigned int g_done[NCTR][ROWB];
__device__ unsigned int g_tile_ctr;

// ---------------- tile configuration ----------------
static constexpr int BM = 128, BN = 128, BK = 32;
static constexpr int STAGES = 4, NTHREADS = 256;
static constexpr int STR  = BK + 8;
static constexpr int ASZ  = BM * STR;
static constexpr int BSZ  = BN * STR;
static constexpr int SMEM_BYTES = STAGES * (ASZ + BSZ) * 2; // 81920

__device__ __forceinline__ void ldmx4(uint32_t& r0, uint32_t& r1,
                                      uint32_t& r2, uint32_t& r3, uint32_t a) {
    asm volatile("ldmatrix.sync.aligned.m8n8.x4.shared.b16 {%0,%1,%2,%3}, [%4];"
                 : "=r"(r0), "=r"(r1), "=r"(r2), "=r"(r3) : "r"(a));
}
__device__ __forceinline__ float tanh_ap(float x) {
    float y;
    asm("tanh.approx.f32 %0, %1;" : "=f"(y) : "f"(x));
    return y;
}
__device__ __forceinline__ void spin_ge(volatile unsigned int* c, unsigned int v) {
    while (*c < v) __nanosleep(64);
}

// acc = A[bm*128.., :K] @ B[bn*128.., :K]^T
__device__ __forceinline__ void mainloop_f16(
    const __half* __restrict__ A, const __half* __restrict__ Bw,
    int K, int bm, int bn, __half* As, __half* Bs,
    float (&acc)[4][4][4])
{
    const int tid  = threadIdx.x;
    const int wid  = tid >> 5, lane = tid & 31;
    const int warp_m = wid & 1, warp_n = wid >> 1;
    const int KT = K / BK;

#pragma unroll
    for (int a = 0; a < 4; ++a)
#pragma unroll
        for (int b = 0; b < 4; ++b)
#pragma unroll
            for (int c = 0; c < 4; ++c) acc[a][b][c] = 0.f;

    auto load_tile = [&](int kt, int stage) {
        const __half* Ag = A + (size_t)(bm * BM) * K + (size_t)kt * BK;
        __half* Asb = As + stage * ASZ;
#pragma unroll
        for (int i = 0; i < 2; ++i) {
            int lin = i * NTHREADS + tid;
            int r = lin >> 2, c = (lin & 3) << 3;
            uint32_t sa = (uint32_t)__cvta_generic_to_shared(Asb + r * STR + c);
            asm volatile("cp.async.cg.shared.global [%0], [%1], 16;"
                         :: "r"(sa), "l"(Ag + (size_t)r * K + c));
        }
        const __half* Bg = Bw + (size_t)(bn * BN) * K + (size_t)kt * BK;
        __half* Bsb = Bs + stage * BSZ;
#pragma unroll
        for (int i = 0; i < 2; ++i) {
            int lin = i * NTHREADS + tid;
            int r = lin >> 2, c = (lin & 3) << 3;
            uint32_t sa = (uint32_t)__cvta_generic_to_shared(Bsb + r * STR + c);
            asm volatile("cp.async.cg.shared.global [%0], [%1], 16;"
                         :: "r"(sa), "l"(Bg + (size_t)r * K + c));
        }
        asm volatile("cp.async.commit_group;");
    };

    const int a_row  = warp_m * 64 + (lane & 15);
    const int a_koff = (lane >> 4) << 3;
    const int b_row  = warp_n * 32 + (lane & 7) + ((lane >> 4) << 3);
    const int b_koff = ((lane >> 3) & 1) << 3;

    for (int s = 0; s < STAGES - 1 && s < KT; ++s) load_tile(s, s);

    for (int kt = 0; kt < KT; ++kt) {
        if (kt < KT - (STAGES - 1))
            asm volatile("cp.async.wait_group %0;" :: "n"(STAGES - 2));
        else
            asm volatile("cp.async.wait_group 0;");
        __syncthreads();

        int pf = kt + STAGES - 1;
        if (pf < KT) load_tile(pf, pf % STAGES);

        const __half* Asb = As + (kt % STAGES) * ASZ;
        const __half* Bsb = Bs + (kt % STAGES) * BSZ;
        const uint32_t a_base = (uint32_t)__cvta_generic_to_shared(
            Asb + (size_t)a_row * STR + a_koff);
        const uint32_t b_base = (uint32_t)__cvta_generic_to_shared(
            Bsb + (size_t)b_row * STR + b_koff);

#pragma unroll
        for (int ks = 0; ks < BK / 16; ++ks) {
            uint32_t af[4][4], bf[4][2];
#pragma unroll
            for (int mi = 0; mi < 4; ++mi)
                ldmx4(af[mi][0], af[mi][1], af[mi][2], af[mi][3],
                      a_base + (mi * 16 * STR + ks * 16) * 2);
#pragma unroll
            for (int np = 0; np < 2; ++np)
                ldmx4(bf[np*2][0], bf[np*2][1], bf[np*2+1][0], bf[np*2+1][1],
                      b_base + (np * 16 * STR + ks * 16) * 2);
#pragma unroll
            for (int mi = 0; mi < 4; ++mi)
#pragma unroll
                for (int ni = 0; ni < 4; ++ni) {
                    asm volatile(
                        "mma.sync.aligned.m16n8k16.row.col.f32.f16.f16.f32 "
                        "{%0,%1,%2,%3}, {%4,%5,%6,%7}, {%8,%9}, {%0,%1,%2,%3};"
                        : "+f"(acc[mi][ni][0]), "+f"(acc[mi][ni][1]),
                          "+f"(acc[mi][ni][2]), "+f"(acc[mi][ni][3])
                        : "r"(af[mi][0]), "r"(af[mi][1]), "r"(af[mi][2]), "r"(af[mi][3]),
                          "r"(bf[ni][0]), "r"(bf[ni][1]));
                }
        }
    }
}

// ---------------------------------------------------------------------------
// launch A: merged independent prologue GEMMs (768 one-tile blocks)
//   blk 0..63    W21  = h16(W1a^T @ W2^T)
//   blk 64..127  W2ro = h16(Wro^T @ W2^T)
//   blk 128..255 g    = h16(x0@Wpe + b_pe)
//   blk 256..767 z0h  = h16(x0@Whi + b_hi)
// ---------------------------------------------------------------------------
__global__ __launch_bounds__(NTHREADS, 2)
void gemm_indep(const __half* __restrict__ x0h,
                const __half* __restrict__ wpe, const __half* __restrict__ whi,
                const __half* __restrict__ w1a, const __half* __restrict__ wro,
                const __half* __restrict__ w2h,
                __half* __restrict__ w21, __half* __restrict__ w2ro,
                __half* __restrict__ gh, __half* __restrict__ z0h,
                const float* __restrict__ b_pe, const float* __restrict__ b_hi)
{
    extern __shared__ __half smem[];
    __half* As = smem;
    __half* Bs = smem + STAGES * ASZ;

    const int v = blockIdx.x;
    const __half* A;
    const __half* Bw;
    __half* C;
    const float* bias = nullptr;
    int K = HID, N = HID, bm, bn;

    if (v < 64)        { A = w1a; Bw = w2h; C = w21;  bm = v >> 3; bn = v & 7; }
    else if (v < 128)  { A = wro; Bw = w2h; C = w2ro; int t = v - 64; bm = t >> 3; bn = t & 7; }
    else if (v < 256)  { A = x0h; Bw = wpe; C = gh; bias = b_pe; K = DIN; N = PATHD;
                         int t = v - 128; bm = t >> 1; bn = t & 1; }
    else               { A = x0h; Bw = whi; C = z0h; bias = b_hi; K = DIN;
                         int t = v - 256; bm = t >> 3; bn = t & 7; }

    float acc[4][4][4];
    mainloop_f16(A, Bw, K, bm, bn, As, Bs, acc);

    const int tid = threadIdx.x, wid = tid >> 5, lane = tid & 31;
    const int gid = lane >> 2, tig = lane & 3;
    const int rbase = bm * BM + (wid & 1) * 64;
    const int cbase = bn * BN + (wid >> 1) * 32;
#pragma unroll
    for (int mi = 0; mi < 4; ++mi)
#pragma unroll
        for (int h2 = 0; h2 < 2; ++h2) {
            int row = rbase + mi * 16 + h2 * 8 + gid;
#pragma unroll
            for (int ni = 0; ni < 4; ++ni) {
                int col = cbase + ni * 8 + tig * 2;
                size_t off = (size_t)row * N + col;
                float v0 = acc[mi][ni][h2 * 2 + 0];
                float v1 = acc[mi][ni][h2 * 2 + 1];
                if (bias) { v0 += bias[col]; v1 += bias[col + 1]; }
                *reinterpret_cast<__half2*>(C + off) = __floats2half2_rn(v0, v1);
            }
        }
}

// ---------------------------------------------------------------------------
// persistent kernel: q -> y0 -> 49 chain -> o1 -> final
// ---------------------------------------------------------------------------
__global__ __launch_bounds__(NTHREADS, 2)
void cde_chain(const __half* __restrict__ gh, const __half* __restrict__ w1b,
               const __half* __restrict__ w1a,
               const __half* __restrict__ W21, const __half* __restrict__ wro,
               const __half* __restrict__ w2ro,
               const __half* __restrict__ z0h,
               __half* __restrict__ u0s, __half* __restrict__ u1s,
               __half* __restrict__ Sh, __half* __restrict__ qh,
               float* __restrict__ yS,
               float* __restrict__ o1, float* __restrict__ out,
               const float* __restrict__ cv,
               const float* __restrict__ b1t, const float* __restrict__ b2ro,
               float dt)
{
    extern __shared__ __half smem[];
    __half* As = smem;
    __half* Bs = smem + STAGES * ASZ;
    __shared__ unsigned int s_tile;

    const int tid = threadIdx.x, wid = tid >> 5, lane = tid & 31;
    const int gid = lane >> 2, tig = lane & 3;

    while (true) {
        if (tid == 0) s_tile = atomicAdd(&g_tile_ctr, 1u);
        __syncthreads();
        unsigned int v = s_tile;
        if (v >= (unsigned)S_END) break;

        // kind: 0=q 1=y0 2=chain 3=o1 4=final
        int kind, gidx = 0, t;
        if (v < (unsigned)S_Y0)       { kind = 0; t = v; }
        else if (v < (unsigned)S_CH)  { kind = 1; t = v - S_Y0; }
        else if (v < (unsigned)S_O1)  { kind = 2; gidx = (v - S_CH) >> 9; t = (v - S_CH) & 511; }
        else if (v < (unsigned)S_FIN) { kind = 3; t = v - S_O1; }
        else                          { kind = 4; t = v - S_FIN; }
        const int bm = t >> 3, bn = t & 7;

        // dependencies (row-block granularity; strictly earlier slots only)
        if (tid == 0) {
            if (kind == 1) {
                spin_ge(&g_done[0][bm], 8u);                 // q row
                __threadfence();
            } else if (kind == 2) {
                spin_ge(&g_done[1 + gidx][bm], 8u);          // y0 / prev chain
                __threadfence();
            } else if (kind == 4) {
                spin_ge(&g_done[1 + NCHAIN][bm], 8u);        // chain 48
                spin_ge(&g_done[51][bm], 8u);                // o1
                __threadfence();
            }
        }
        __syncthreads();

        const __half* A;
        const __half* Bw;
        int K = HID;
        if (kind == 0)      { A = gh;  Bw = w1b; K = PATHD; }
        else if (kind == 1) { A = z0h; Bw = w1a; }
        else if (kind == 2) { A = ((gidx + 1) & 1) ? u1s : u0s; Bw = W21; }
        else if (kind == 3) { A = z0h; Bw = wro; }
        else                { A = Sh;  Bw = w2ro; }

        float acc[4][4][4];
        mainloop_f16(A, Bw, K, bm, bn, As, Bs, acc);

        const int rbase = bm * BM + (wid & 1) * 64;
        const int cbase = bn * BN + (wid >> 1) * 32;

        if (kind == 0) {
#pragma unroll
            for (int mi = 0; mi < 4; ++mi)
#pragma unroll
                for (int h2 = 0; h2 < 2; ++h2) {
                    int row = rbase + mi * 16 + h2 * 8 + gid;
#pragma unroll
                    for (int ni = 0; ni < 4; ++ni) {
                        int col = cbase + ni * 8 + tig * 2;
                        size_t off = (size_t)row * HID + col;
                        *reinterpret_cast<__half2*>(qh + off) = __floats2half2_rn(
                            acc[mi][ni][h2 * 2 + 0] + cv[col],
                            acc[mi][ni][h2 * 2 + 1] + cv[col + 1]);
                    }
                }
        } else if (kind == 1) {
#pragma unroll
            for (int mi = 0; mi < 4; ++mi)
#pragma unroll
                for (int h2 = 0; h2 < 2; ++h2) {
                    int row = rbase + mi * 16 + h2 * 8 + gid;
#pragma unroll
                    for (int ni = 0; ni < 4; ++ni) {
                        int col = cbase + ni * 8 + tig * 2;
                        size_t uoff  = (size_t)row * HID + col;
                        size_t ysoff = (size_t)row * (2 * HID) + col * 2;
                        float a0 = acc[mi][ni][h2 * 2 + 0];
                        float a1 = acc[mi][ni][h2 * 2 + 1];
                        float2 qe = __half22float2(
                            *reinterpret_cast<const __half2*>(qh + uoff));
                        float u0 = tanh_ap(a0 + dt * qe.x + b1t[col]);
                        float u1 = tanh_ap(a1 + dt * qe.y + b1t[col + 1]);
                        *reinterpret_cast<__half2*>(u1s + uoff) =
                            __floats2half2_rn(u0, u1);
                        *reinterpret_cast<float4*>(yS + ysoff) =
                            make_float4(a0, a1, u0, u1);
                    }
                }
        } else if (kind == 2) {
            __half* Cu = (gidx & 1) ? u1s : u0s;
            const float tcoef = dt * (float)(gidx + 2);
            const bool last = (gidx == NCHAIN - 1);
#pragma unroll
            for (int mi = 0; mi < 4; ++mi)
#pragma unroll
                for (int h2 = 0; h2 < 2; ++h2) {
                    int row = rbase + mi * 16 + h2 * 8 + gid;
#pragma unroll
                    for (int ni = 0; ni < 4; ++ni) {
                        int col = cbase + ni * 8 + tig * 2;
                        size_t uoff  = (size_t)row * HID + col;
                        size_t ysoff = (size_t)row * (2 * HID) + col * 2;
                        float a0 = acc[mi][ni][h2 * 2 + 0];
                        float a1 = acc[mi][ni][h2 * 2 + 1];
                        float4 ys = __ldcg(reinterpret_cast<const float4*>(yS + ysoff));
                        ys.x += dt * a0;
                        ys.y += dt * a1;
                        float2 qe = __half22float2(
                            *reinterpret_cast<const __half2*>(qh + uoff));
                        float u0 = tanh_ap(ys.x + tcoef * qe.x + b1t[col]);
                        float u1 = tanh_ap(ys.y + tcoef * qe.y + b1t[col + 1]);
                        ys.z += u0;
                        ys.w += u1;
                        *reinterpret_cast<__half2*>(Cu + uoff) =
                            __floats2half2_rn(u0, u1);
                        *reinterpret_cast<float4*>(yS + ysoff) = ys;
                        if (last)
                            *reinterpret_cast<__half2*>(Sh + uoff) =
                                __floats2half2_rn(ys.z, ys.w);
                    }
                }
        } else if (kind == 3) {
#pragma unroll
            for (int mi = 0; mi < 4; ++mi)
#pragma unroll
                for (int h2 = 0; h2 < 2; ++h2) {
                    int row = rbase + mi * 16 + h2 * 8 + gid;
#pragma unroll
                    for (int ni = 0; ni < 4; ++ni) {
                        int col = cbase + ni * 8 + tig * 2;
                        size_t off = (size_t)row * HID + col;
                        *reinterpret_cast<float2*>(o1 + off) = make_float2(
                            acc[mi][ni][h2 * 2 + 0], acc[mi][ni][h2 * 2 + 1]);
                    }
                }
        } else {
#pragma unroll
            for (int mi = 0; mi < 4; ++mi)
#pragma unroll
                for (int h2 = 0; h2 < 2; ++h2) {
                    int row = rbase + mi * 16 + h2 * 8 + gid;
#pragma unroll
                    for (int ni = 0; ni < 4; ++ni) {
                        int col = cbase + ni * 8 + tig * 2;
                        size_t off = (size_t)row * HID + col;
                        float2 ov = __ldcg(reinterpret_cast<const float2*>(o1 + off));
                        *reinterpret_cast<float2*>(out + off) = make_float2(
                            ov.x + dt * acc[mi][ni][h2 * 2 + 0] + b2ro[col],
                            ov.y + dt * acc[mi][ni][h2 * 2 + 1] + b2ro[col + 1]);
                    }
                }
        }

        if (kind != 4) {
            __threadfence();
            __syncthreads();
            if (tid == 0) {
                int ci;
                if (kind == 0)      ci = 0;
                else if (kind == 1) ci = 1;
                else if (kind == 2) ci = 2 + gidx;
                else                ci = 51;
                atomicAdd(&g_done[ci][bm], 1u);
            }
        }
    }
}

// ---------------------------------------------------------------------------
// prep kernels
// ---------------------------------------------------------------------------
__global__ void zero_sync()
{
    int i = blockIdx.x * blockDim.x + threadIdx.x;
    unsigned int* p = &g_done[0][0];
    int n = NCTR * ROWB;
    if (i < n) p[i] = 0;
    if (i == n) g_tile_ctr = 0;
}

__global__ void transpose_h16(const float* __restrict__ in, __half* __restrict__ out,
                              int K, int N)
{
    __shared__ float t[32][33];
    const int k0 = blockIdx.y * 32, n0 = blockIdx.x * 32;
    const int x = threadIdx.x, y = threadIdx.y;
#pragma unroll
    for (int i = 0; i < 32; i += 8)
        t[y + i][x] = in[(size_t)(k0 + y + i) * N + n0 + x];
    __syncthreads();
#pragma unroll
    for (int i = 0; i < 32; i += 8)
        out[(size_t)(n0 + y + i) * K + k0 + x] = __float2half_rn(t[x][y + i]);
}

__global__ void to_h16(const float4* __restrict__ in, __half2* __restrict__ out, int n4)
{
    int i = blockIdx.x * blockDim.x + threadIdx.x;
    if (i < n4) {
        float4 v = in[i];
        out[i * 2 + 0] = __floats2half2_rn(v.x, v.y);
        out[i * 2 + 1] = __floats2half2_rn(v.z, v.w);
    }
}

__global__ void vecmat_h16(const __half* __restrict__ Wt,
                           const float* __restrict__ vec,
                           const float* __restrict__ add,
                           float* __restrict__ outv)
{
    __shared__ float red[256];
    int n = blockIdx.x;
    float s = 0.f;
    for (int j = threadIdx.x; j < HID; j += 256)
        s += vec[j] * __half2float(Wt[(size_t)n * HID + j]);
    red[threadIdx.x] = s;
    __syncthreads();
    for (int k = 128; k > 0; k >>= 1) {
        if (threadIdx.x < k) red[threadIdx.x] += red[threadIdx.x + k];
        __syncthreads();
    }
    if (threadIdx.x == 0) outv[n] = red[0] + (add ? add[n] : 0.f);
}

__global__ void make_b1t(const float* __restrict__ b1, const float* __restrict__ cv,
                         float* __restrict__ b1t, float dt)
{
    int i = threadIdx.x + blockIdx.x * blockDim.x;
    if (i < HID) b1t[i] = b1[i] - dt * cv[i];
}

extern "C" void kernel_launch(void* const* d_in, const int* in_sizes, int n_in,
                              void* d_out, int out_size)
{
    const float* x0   = (const float*)d_in[0];
    const float* W_pe = (const float*)d_in[1];
    const float* b_pe = (const float*)d_in[2];
    const float* W_hi = (const float*)d_in[3];
    const float* b_hi = (const float*)d_in[4];
    const float* W1   = (const float*)d_in[5];
    const float* b1   = (const float*)d_in[6];
    const float* W2   = (const float*)d_in[7];
    const float* b2   = (const float*)d_in[8];
    const float* W_ro = (const float*)d_in[9];
    const float* b_ro = (const float*)d_in[10];
    float* out = (float*)d_out;

    __half *x0h, *gh, *qh, *z0h, *u0s, *u1s, *Shp;
    __half *wpe, *whi, *w1a, *w1b, *wro, *w2h, *w21, *w2ro;
    float *yS, *o1, *cv, *b1t, *b2ro;
    cudaGetSymbolAddress((void**)&x0h, x0h_buf);
    cudaGetSymbolAddress((void**)&gh,  gh_buf);
    cudaGetSymbolAddress((void**)&qh,  qh_buf);
    cudaGetSymbolAddress((void**)&z0h, z0h_buf);
    cudaGetSymbolAddress((void**)&u0s, u0_buf);
    cudaGetSymbolAddress((void**)&u1s, u1_buf);
    cudaGetSymbolAddress((void**)&Shp, Sh_buf);
    cudaGetSymbolAddress((void**)&yS,  yS_buf);
    cudaGetSymbolAddress((void**)&o1,  o1_buf);
    cudaGetSymbolAddress((void**)&wpe, WpeT);
    cudaGetSymbolAddress((void**)&whi, WhiT);
    cudaGetSymbolAddress((void**)&w1a, W1aT);
    cudaGetSymbolAddress((void**)&w1b, W1bT);
    cudaGetSymbolAddress((void**)&wro, WroT);
    cudaGetSymbolAddress((void**)&w2h, W2h);
    cudaGetSymbolAddress((void**)&w21, W21T_b);
    cudaGetSymbolAddress((void**)&w2ro, W2roT_b);
    cudaGetSymbolAddress((void**)&cv,  cvec_b);
    cudaGetSymbolAddress((void**)&b1t, b1t_b);
    cudaGetSymbolAddress((void**)&b2ro, b2ro_b);

    const float dt = 1.0f / (float)NSTEP;
    dim3 tb32(32, 8);

    int nthr = NCTR * ROWB + 1;
    zero_sync<<<(nthr + 255) / 256, 256>>>();

    transpose_h16<<<dim3(PATHD/32, DIN/32), tb32>>>(W_pe, wpe, DIN, PATHD);
    transpose_h16<<<dim3(HID/32,   DIN/32), tb32>>>(W_hi, whi, DIN, HID);
    transpose_h16<<<dim3(HID/32,   HID/32), tb32>>>(W1,   w1a, HID, HID);
    transpose_h16<<<dim3(HID/32,   PATHD/32), tb32>>>(W1 + (size_t)HID * HID, w1b, PATHD, HID);
    transpose_h16<<<dim3(HID/32,   HID/32), tb32>>>(W_ro, wro, HID, HID);

    int n4 = (BATCH * DIN) / 4;
    to_h16<<<(n4 + 255) / 256, 256>>>((const float4*)x0, (__half2*)x0h, n4);
    int w4 = (HID * HID) / 4;
    to_h16<<<(w4 + 255) / 256, 256>>>((const float4*)W2, (__half2*)w2h, w4);

    vecmat_h16<<<HID, 256>>>(w1a, b2, nullptr, cv);   // c = b2@W1a
    vecmat_h16<<<HID, 256>>>(wro, b2, b_ro, b2ro);    // b2ro = b2@Wro + b_ro
    make_b1t<<<4, 256>>>(b1, cv, b1t, dt);

    // launch A: all independent GEMMs in one grid
    cudaFuncSetAttribute(gemm_indep,
                         cudaFuncAttributeMaxDynamicSharedMemorySize, SMEM_BYTES);
    gemm_indep<<<768, NTHREADS, SMEM_BYTES>>>(
        x0h, wpe, whi, w1a, wro, w2h, w21, w2ro, gh, z0h, b_pe, b_hi);

    // persistent: q -> y0 -> chain -> o1 -> final
    int dev = 0, nsm = 148;
    cudaGetDevice(&dev);
    cudaDeviceGetAttribute(&nsm, cudaDevAttrMultiProcessorCount, dev);
    cudaFuncSetAttribute(cde_chain,
                         cudaFuncAttributeMaxDynamicSharedMemorySize, SMEM_BYTES);
    cde_chain<<<2 * nsm, NTHREADS, SMEM_BYTES>>>(
        gh, w1b, w1a, w21, wro, w2ro, z0h, u0s, u1s, Shp, qh,
        yS, o1, out, cv, b1t, b2ro, dt);
}